// round 3
// baseline (speedup 1.0000x reference)
#include <cuda_runtime.h>
#include <cstdint>
#include <cstddef>

#define Nn 50000
#define Ee 800000
#define Cc 64

// ---------------- scratch (static device globals; no allocation) ----------------
__device__ float g_v   [Nn * Cc];
__device__ float g_asrc[Nn * Cc];
__device__ float g_adst[Nn * Cc];
__device__ float g_m   [Nn * Cc];
__device__ float g_s   [Nn * Cc];
__device__ float g_acc [Nn * Cc];
__device__ float g_logits[(size_t)Ee * Cc];
__device__ float g_delta [(size_t)Ee * Cc];

// ---------------- helpers ----------------
__device__ __forceinline__ void atomicMaxFloat(float* addr, float val) {
    // classic signed/unsigned split: monotone toward max for all sign mixes,
    // init value is -inf (0xFF800000)
    if (val >= 0.0f) atomicMax((int*)addr, __float_as_int(val));
    else             atomicMin((unsigned int*)addr, __float_as_uint(val));
}

// 64x64 matmul for 2 "nodes" held distributed across a warp:
// lane l holds in[l] (ia) and in[l+32] (ib) per node; Wf2[k*32+l] = (W[k][l], W[k][l+32])
__device__ __forceinline__ void mm2(const float2* __restrict__ Wf2,
                                    float i0a, float i0b, float i1a, float i1b,
                                    float2& o0, float2& o1) {
    const int lane = threadIdx.x & 31;
#pragma unroll
    for (int k = 0; k < 32; k++) {
        float v0 = __shfl_sync(0xffffffffu, i0a, k);
        float v1 = __shfl_sync(0xffffffffu, i1a, k);
        float2 wv = Wf2[k * 32 + lane];
        o0.x = fmaf(v0, wv.x, o0.x); o0.y = fmaf(v0, wv.y, o0.y);
        o1.x = fmaf(v1, wv.x, o1.x); o1.y = fmaf(v1, wv.y, o1.y);
    }
#pragma unroll
    for (int k = 0; k < 32; k++) {
        float v0 = __shfl_sync(0xffffffffu, i0b, k);
        float v1 = __shfl_sync(0xffffffffu, i1b, k);
        float2 wv = Wf2[(k + 32) * 32 + lane];
        o0.x = fmaf(v0, wv.x, o0.x); o0.y = fmaf(v0, wv.y, o0.y);
        o1.x = fmaf(v1, wv.x, o1.x); o1.y = fmaf(v1, wv.y, o1.y);
    }
}

// ---------------- kernel 0: init reduction buffers ----------------
__global__ __launch_bounds__(256) void init_kernel() {
    int i = blockIdx.x * blockDim.x + threadIdx.x;
    if (i < Nn * Cc) {
        ((unsigned int*)g_m)[i] = 0xFF800000u;  // -inf
        g_s[i]   = 0.0f;
        g_acc[i] = 0.0f;
    }
}

// ---------------- kernel 1: node projections ----------------
// h = relu(x@W_in + b_in); v = h@W_lin; a_src = h@W_src; a_dst = h@W_dst
__global__ __launch_bounds__(256) void node_proj_kernel(
    const float* __restrict__ x,
    const float* __restrict__ Win,  const float* __restrict__ bin,
    const float* __restrict__ Wlin, const float* __restrict__ Wsrc,
    const float* __restrict__ Wdst)
{
    extern __shared__ float smem[];
    float2* sW = (float2*)smem;        // 4 matrices x 2048 float2 (interleaved c,c+32)
    float*  sb = smem + 4 * 4096;      // 64 floats (b_in)
    int tid = threadIdx.x;
    for (int i = tid; i < 2048; i += 256) {
        int k = i >> 5, c = i & 31;
        sW[0 * 2048 + i] = make_float2(Win [k * 64 + c], Win [k * 64 + c + 32]);
        sW[1 * 2048 + i] = make_float2(Wlin[k * 64 + c], Wlin[k * 64 + c + 32]);
        sW[2 * 2048 + i] = make_float2(Wsrc[k * 64 + c], Wsrc[k * 64 + c + 32]);
        sW[3 * 2048 + i] = make_float2(Wdst[k * 64 + c], Wdst[k * 64 + c + 32]);
    }
    if (tid < 64) sb[tid] = bin[tid];
    __syncthreads();

    int lane  = tid & 31;
    int warpG = blockIdx.x * 8 + (tid >> 5);
    int nW    = gridDim.x * 8;
    for (int p = warpG; p < Nn / 2; p += nW) {
        int n0 = 2 * p, n1 = n0 + 1;
        float x0a = x[n0 * 64 + lane], x0b = x[n0 * 64 + 32 + lane];
        float x1a = x[n1 * 64 + lane], x1b = x[n1 * 64 + 32 + lane];

        float2 h0 = make_float2(sb[lane], sb[lane + 32]);
        float2 h1 = h0;
        mm2(sW, x0a, x0b, x1a, x1b, h0, h1);
        h0.x = fmaxf(h0.x, 0.0f); h0.y = fmaxf(h0.y, 0.0f);
        h1.x = fmaxf(h1.x, 0.0f); h1.y = fmaxf(h1.y, 0.0f);

        float2 v0 = make_float2(0.f, 0.f), v1 = v0;
        mm2(sW + 1 * 2048, h0.x, h0.y, h1.x, h1.y, v0, v1);
        g_v[n0 * 64 + lane] = v0.x; g_v[n0 * 64 + 32 + lane] = v0.y;
        g_v[n1 * 64 + lane] = v1.x; g_v[n1 * 64 + 32 + lane] = v1.y;

        float2 s0 = make_float2(0.f, 0.f), s1 = s0;
        mm2(sW + 2 * 2048, h0.x, h0.y, h1.x, h1.y, s0, s1);
        g_asrc[n0 * 64 + lane] = s0.x; g_asrc[n0 * 64 + 32 + lane] = s0.y;
        g_asrc[n1 * 64 + lane] = s1.x; g_asrc[n1 * 64 + 32 + lane] = s1.y;

        float2 d0 = make_float2(0.f, 0.f), d1 = d0;
        mm2(sW + 3 * 2048, h0.x, h0.y, h1.x, h1.y, d0, d1);
        g_adst[n0 * 64 + lane] = d0.x; g_adst[n0 * 64 + 32 + lane] = d0.y;
        g_adst[n1 * 64 + lane] = d1.x; g_adst[n1 * 64 + 32 + lane] = d1.y;
    }
}

// ---------------- kernel 2: edge pass 1 (delta, logits, segment max) ----------------
// warp processes 8 edges per tile; smem holds Wp1/Wp2/Wa1/Wa2 + per-warp buffers
__global__ __launch_bounds__(256) void edge_pass1_kernel(
    const float* __restrict__ pos, const int* __restrict__ ei,
    const float* __restrict__ Wp1, const float* __restrict__ bp1,
    const float* __restrict__ Wp2, const float* __restrict__ bp2,
    const float* __restrict__ Wa1, const float* __restrict__ ba1,
    const float* __restrict__ Wa2, const float* __restrict__ ba2)
{
    extern __shared__ float smem[];
    float2* sWp2 = (float2*)smem;                 // [0,4096) floats
    float2* sWa1 = (float2*)(smem + 4096);        // [4096,8192)
    float2* sWa2 = (float2*)(smem + 8192);        // [8192,12288)
    float*  sWp1 = smem + 12288;                  // 192
    float*  sbp1 = smem + 12480;                  // 64
    float*  sbp2 = smem + 12544;
    float*  sba1 = smem + 12608;
    float*  sba2 = smem + 12672;
    float*  sU   = smem + 12736;                  // 8 warps * 8 edges * 64
    float*  sT   = smem + 16832;                  // 8 warps * 8 edges * 64
    float*  sRel = smem + 20928;                  // 8 warps * 8 edges * 4
    int*    sIdx = (int*)(smem + 21184);          // 8 warps * 8 edges * 2

    int tid = threadIdx.x;
    for (int i = tid; i < 2048; i += 256) {
        int k = i >> 5, c = i & 31;
        sWp2[i] = make_float2(Wp2[k * 64 + c], Wp2[k * 64 + c + 32]);
        sWa1[i] = make_float2(Wa1[k * 64 + c], Wa1[k * 64 + c + 32]);
        sWa2[i] = make_float2(Wa2[k * 64 + c], Wa2[k * 64 + c + 32]);
    }
    if (tid < 192) sWp1[tid] = Wp1[tid];
    if (tid < 64) { sbp1[tid] = bp1[tid]; sbp2[tid] = bp2[tid];
                    sba1[tid] = ba1[tid]; sba2[tid] = ba2[tid]; }
    __syncthreads();

    const int lane = tid & 31, w = tid >> 5;
    float* myU   = sU   + w * 8 * 64;
    float* myT   = sT   + w * 8 * 64;
    float* myRel = sRel + w * 8 * 4;
    int*   myIdx = sIdx + w * 8 * 2;

    int warpG = blockIdx.x * 8 + w;
    int nW    = gridDim.x * 8;
    const int nTiles = Ee / 8;   // E divisible by 8 -> no tail

    for (int t = warpG; t < nTiles; t += nW) {
        int eb = t * 8;
        if (lane < 8) {
            int ge = eb + lane;
            int s = ei[ge], d = ei[Ee + ge];
            myIdx[lane * 2]     = s;
            myIdx[lane * 2 + 1] = d;
            myRel[lane * 4 + 0] = pos[d * 3 + 0] - pos[s * 3 + 0];
            myRel[lane * 4 + 1] = pos[d * 3 + 1] - pos[s * 3 + 1];
            myRel[lane * 4 + 2] = pos[d * 3 + 2] - pos[s * 3 + 2];
        }
        __syncwarp();

        // stage 1: u = relu(rel @ Wp1 + bp1)
#pragma unroll
        for (int e = 0; e < 8; e++) {
            float r0 = myRel[e * 4], r1 = myRel[e * 4 + 1], r2 = myRel[e * 4 + 2];
            float a = sbp1[lane], b = sbp1[lane + 32];
            a = fmaf(r0, sWp1[lane],        a); b = fmaf(r0, sWp1[lane + 32],        b);
            a = fmaf(r1, sWp1[64 + lane],   a); b = fmaf(r1, sWp1[64 + lane + 32],   b);
            a = fmaf(r2, sWp1[128 + lane],  a); b = fmaf(r2, sWp1[128 + lane + 32],  b);
            myU[e * 64 + lane]      = fmaxf(a, 0.0f);
            myU[e * 64 + lane + 32] = fmaxf(b, 0.0f);
        }
        __syncwarp();

        // stage 2: delta = u @ Wp2 + bp2 ; t = delta + a_dst[dst] - a_src[src]
#pragma unroll
        for (int eo = 0; eo < 8; eo += 4) {
            float2 a0 = make_float2(0.f, 0.f), a1 = a0, a2 = a0, a3 = a0;
#pragma unroll
            for (int k = 0; k < 64; k++) {
                float2 wv = sWp2[k * 32 + lane];
                float u0 = myU[(eo + 0) * 64 + k];
                float u1 = myU[(eo + 1) * 64 + k];
                float u2 = myU[(eo + 2) * 64 + k];
                float u3 = myU[(eo + 3) * 64 + k];
                a0.x = fmaf(u0, wv.x, a0.x); a0.y = fmaf(u0, wv.y, a0.y);
                a1.x = fmaf(u1, wv.x, a1.x); a1.y = fmaf(u1, wv.y, a1.y);
                a2.x = fmaf(u2, wv.x, a2.x); a2.y = fmaf(u2, wv.y, a2.y);
                a3.x = fmaf(u3, wv.x, a3.x); a3.y = fmaf(u3, wv.y, a3.y);
            }
            float2 accs[4] = {a0, a1, a2, a3};
#pragma unroll
            for (int i = 0; i < 4; i++) {
                int e = eo + i; size_t ge = (size_t)(eb + e);
                float d0 = accs[i].x + sbp2[lane];
                float d1 = accs[i].y + sbp2[lane + 32];
                g_delta[ge * 64 + lane]      = d0;
                g_delta[ge * 64 + lane + 32] = d1;
                int sN = myIdx[e * 2], dN = myIdx[e * 2 + 1];
                float t0 = d0 + __ldg(&g_adst[dN * 64 + lane])      - __ldg(&g_asrc[sN * 64 + lane]);
                float t1 = d1 + __ldg(&g_adst[dN * 64 + lane + 32]) - __ldg(&g_asrc[sN * 64 + lane + 32]);
                myT[e * 64 + lane]      = t0;
                myT[e * 64 + lane + 32] = t1;
            }
        }
        __syncwarp();

        // stage 3: h2 = relu(t @ Wa1 + ba1) -> myU
#pragma unroll
        for (int eo = 0; eo < 8; eo += 4) {
            float2 a0 = make_float2(0.f, 0.f), a1 = a0, a2 = a0, a3 = a0;
#pragma unroll
            for (int k = 0; k < 64; k++) {
                float2 wv = sWa1[k * 32 + lane];
                float u0 = myT[(eo + 0) * 64 + k];
                float u1 = myT[(eo + 1) * 64 + k];
                float u2 = myT[(eo + 2) * 64 + k];
                float u3 = myT[(eo + 3) * 64 + k];
                a0.x = fmaf(u0, wv.x, a0.x); a0.y = fmaf(u0, wv.y, a0.y);
                a1.x = fmaf(u1, wv.x, a1.x); a1.y = fmaf(u1, wv.y, a1.y);
                a2.x = fmaf(u2, wv.x, a2.x); a2.y = fmaf(u2, wv.y, a2.y);
                a3.x = fmaf(u3, wv.x, a3.x); a3.y = fmaf(u3, wv.y, a3.y);
            }
            float2 accs[4] = {a0, a1, a2, a3};
#pragma unroll
            for (int i = 0; i < 4; i++) {
                int e = eo + i;
                myU[e * 64 + lane]      = fmaxf(accs[i].x + sba1[lane], 0.0f);
                myU[e * 64 + lane + 32] = fmaxf(accs[i].y + sba1[lane + 32], 0.0f);
            }
        }
        __syncwarp();

        // stage 4: logit = h2 @ Wa2 + ba2 ; store + atomic segment max
#pragma unroll
        for (int eo = 0; eo < 8; eo += 4) {
            float2 a0 = make_float2(0.f, 0.f), a1 = a0, a2 = a0, a3 = a0;
#pragma unroll
            for (int k = 0; k < 64; k++) {
                float2 wv = sWa2[k * 32 + lane];
                float u0 = myU[(eo + 0) * 64 + k];
                float u1 = myU[(eo + 1) * 64 + k];
                float u2 = myU[(eo + 2) * 64 + k];
                float u3 = myU[(eo + 3) * 64 + k];
                a0.x = fmaf(u0, wv.x, a0.x); a0.y = fmaf(u0, wv.y, a0.y);
                a1.x = fmaf(u1, wv.x, a1.x); a1.y = fmaf(u1, wv.y, a1.y);
                a2.x = fmaf(u2, wv.x, a2.x); a2.y = fmaf(u2, wv.y, a2.y);
                a3.x = fmaf(u3, wv.x, a3.x); a3.y = fmaf(u3, wv.y, a3.y);
            }
            float2 accs[4] = {a0, a1, a2, a3};
#pragma unroll
            for (int i = 0; i < 4; i++) {
                int e = eo + i; size_t ge = (size_t)(eb + e);
                float l0 = accs[i].x + sba2[lane];
                float l1 = accs[i].y + sba2[lane + 32];
                g_logits[ge * 64 + lane]      = l0;
                g_logits[ge * 64 + lane + 32] = l1;
                int dN = myIdx[e * 2 + 1];
                atomicMaxFloat(&g_m[dN * 64 + lane],      l0);
                atomicMaxFloat(&g_m[dN * 64 + lane + 32], l1);
            }
        }
        __syncwarp();
    }
}

// ---------------- kernel 3: edge pass 2 (exp + segment sums) ----------------
__global__ __launch_bounds__(256) void edge_pass2_kernel(const int* __restrict__ ei)
{
    int idx = blockIdx.x * blockDim.x + threadIdx.x;  // (edge, 4-ch group)
    int e = idx >> 4;
    if (e >= Ee) return;
    int c = (idx & 15) << 2;
    int sN = ei[e], dN = ei[Ee + e];
    float4 lg = *(const float4*)&g_logits[(size_t)e * 64 + c];
    float4 mm = *(const float4*)&g_m[dN * 64 + c];
    float4 dl = *(const float4*)&g_delta[(size_t)e * 64 + c];
    float4 vv = *(const float4*)&g_v[sN * 64 + c];
    float e0 = __expf(lg.x - mm.x);
    float e1 = __expf(lg.y - mm.y);
    float e2 = __expf(lg.z - mm.z);
    float e3 = __expf(lg.w - mm.w);
    float* sp = &g_s[dN * 64 + c];
    atomicAdd(sp + 0, e0); atomicAdd(sp + 1, e1);
    atomicAdd(sp + 2, e2); atomicAdd(sp + 3, e3);
    float* ap = &g_acc[dN * 64 + c];
    atomicAdd(ap + 0, e0 * (vv.x + dl.x));
    atomicAdd(ap + 1, e1 * (vv.y + dl.y));
    atomicAdd(ap + 2, e2 * (vv.z + dl.z));
    atomicAdd(ap + 3, e3 * (vv.w + dl.w));
}

// ---------------- kernel 4: normalize + lin_out + relu ----------------
__global__ __launch_bounds__(256) void node_out_kernel(
    const float* __restrict__ Wout, const float* __restrict__ bout,
    float* __restrict__ out)
{
    __shared__ float2 sW[2048];
    __shared__ float  sb[64];
    int tid = threadIdx.x;
    for (int i = tid; i < 2048; i += 256) {
        int k = i >> 5, c = i & 31;
        sW[i] = make_float2(Wout[k * 64 + c], Wout[k * 64 + c + 32]);
    }
    if (tid < 64) sb[tid] = bout[tid];
    __syncthreads();

    int lane  = tid & 31;
    int warpG = blockIdx.x * 8 + (tid >> 5);
    int nW    = gridDim.x * 8;
    for (int p = warpG; p < Nn / 2; p += nW) {
        int n0 = 2 * p, n1 = n0 + 1;
        float r0a = g_acc[n0 * 64 + lane]      / (g_s[n0 * 64 + lane]      + 1e-16f);
        float r0b = g_acc[n0 * 64 + 32 + lane] / (g_s[n0 * 64 + 32 + lane] + 1e-16f);
        float r1a = g_acc[n1 * 64 + lane]      / (g_s[n1 * 64 + lane]      + 1e-16f);
        float r1b = g_acc[n1 * 64 + 32 + lane] / (g_s[n1 * 64 + 32 + lane] + 1e-16f);
        float2 o0 = make_float2(0.f, 0.f), o1 = o0;
        mm2(sW, r0a, r0b, r1a, r1b, o0, o1);
        out[n0 * 64 + lane]      = fmaxf(o0.x + sb[lane],      0.0f);
        out[n0 * 64 + 32 + lane] = fmaxf(o0.y + sb[lane + 32], 0.0f);
        out[n1 * 64 + lane]      = fmaxf(o1.x + sb[lane],      0.0f);
        out[n1 * 64 + 32 + lane] = fmaxf(o1.y + sb[lane + 32], 0.0f);
    }
}

// ---------------- launch ----------------
extern "C" void kernel_launch(void* const* d_in, const int* in_sizes, int n_in,
                              void* d_out, int out_size)
{
    const float* x    = (const float*)d_in[0];
    const float* pos  = (const float*)d_in[1];
    const int*   ei   = (const int*)  d_in[2];
    const float* Win  = (const float*)d_in[3];
    const float* bin  = (const float*)d_in[4];
    const float* Wlin = (const float*)d_in[5];
    const float* Wsrc = (const float*)d_in[6];
    const float* Wdst = (const float*)d_in[7];
    const float* Wp1  = (const float*)d_in[8];
    const float* bp1  = (const float*)d_in[9];
    const float* Wp2  = (const float*)d_in[10];
    const float* bp2  = (const float*)d_in[11];
    const float* Wa1  = (const float*)d_in[12];
    const float* ba1  = (const float*)d_in[13];
    const float* Wa2  = (const float*)d_in[14];
    const float* ba2  = (const float*)d_in[15];
    const float* Wout = (const float*)d_in[16];
    const float* bout = (const float*)d_in[17];

    const int nodeSmem = 4 * 16384 + 256;   // 65792 B
    const int p1Smem   = 21312 * 4;         // 85248 B
    cudaFuncSetAttribute(node_proj_kernel,  cudaFuncAttributeMaxDynamicSharedMemorySize, nodeSmem);
    cudaFuncSetAttribute(edge_pass1_kernel, cudaFuncAttributeMaxDynamicSharedMemorySize, p1Smem);

    init_kernel<<<(Nn * Cc + 255) / 256, 256>>>();
    node_proj_kernel<<<444, 256, nodeSmem>>>(x, Win, bin, Wlin, Wsrc, Wdst);
    edge_pass1_kernel<<<296, 256, p1Smem>>>(pos, ei, Wp1, bp1, Wp2, bp2,
                                            Wa1, ba1, Wa2, ba2);
    edge_pass2_kernel<<<(Ee * 16) / 256, 256>>>(ei);
    node_out_kernel<<<592, 256>>>(Wout, bout, (float*)d_out);
}

// round 5
// speedup vs baseline: 2.6567x; 2.6567x over previous
#include <cuda_runtime.h>
#include <cuda_bf16.h>
#include <cstdint>
#include <cstddef>

#define Nn 50000
#define Ee 800000
#define Cc 64

// ---------------- scratch (static device globals; no allocation) ----------------
__device__ float4 g_v4  [Nn * 16];
__device__ float4 g_as4 [Nn * 16];
__device__ float4 g_ad4 [Nn * 16];
__device__ float4 g_s4  [Nn * 16];
__device__ float4 g_acc4[Nn * 16];

// ---------------- helpers ----------------
// split (a,b) fp32 pair into bf16x2 hi word + bf16x2 lo-residual word.
// word layout: lower f16 = a, upper f16 = b.
__device__ __forceinline__ void pack_hl(float a, float b, uint32_t& h, uint32_t& l) {
    uint32_t hw;
    asm("cvt.rn.bf16x2.f32 %0, %1, %2;" : "=r"(hw) : "f"(b), "f"(a));
    __nv_bfloat162 h2 = *reinterpret_cast<__nv_bfloat162*>(&hw);
    float la = a - __bfloat162float(h2.x);
    float lb = b - __bfloat162float(h2.y);
    uint32_t lw;
    asm("cvt.rn.bf16x2.f32 %0, %1, %2;" : "=r"(lw) : "f"(lb), "f"(la));
    h = hw; l = lw;
}

__device__ __forceinline__ uint32_t pack_bf2(float a, float b) {
    uint32_t w;
    asm("cvt.rn.bf16x2.f32 %0, %1, %2;" : "=r"(w) : "f"(b), "f"(a));
    return w;
}

__device__ __forceinline__ void red4(float4* p, float a, float b, float c, float d) {
    asm volatile("red.global.add.v4.f32 [%0], {%1, %2, %3, %4};"
                 :: "l"(p), "f"(a), "f"(b), "f"(c), "f"(d) : "memory");
}

// m16n8k16 bf16 MMA, fp32 accumulate in-place
__device__ __forceinline__ void mma_bf16(float* d, const uint32_t* a, uint2 b) {
    asm volatile(
        "mma.sync.aligned.m16n8k16.row.col.f32.bf16.bf16.f32 "
        "{%0,%1,%2,%3},{%4,%5,%6,%7},{%8,%9},{%0,%1,%2,%3};"
        : "+f"(d[0]), "+f"(d[1]), "+f"(d[2]), "+f"(d[3])
        : "r"(a[0]), "r"(a[1]), "r"(a[2]), "r"(a[3]), "r"(b.x), "r"(b.y));
}

// one 32x64x64 GEMM = 2 m16-tiles, 3 split-bf16 products (AhBh, AlBh, AhBl)
__device__ __forceinline__ void gemm3p(
    float* D0, float* D1,
    const uint32_t* A0h, const uint32_t* A0l,
    const uint32_t* A1h, const uint32_t* A1l,
    const uint2* __restrict__ bfH, const uint2* __restrict__ bfL, int lane)
{
#pragma unroll
    for (int kt = 0; kt < 4; kt++) {
#pragma unroll
        for (int nt = 0; nt < 8; nt++) {
            uint2 bh = bfH[(kt * 8 + nt) * 32 + lane];
            mma_bf16(D0 + nt * 4, A0h + kt * 4, bh);
            mma_bf16(D1 + nt * 4, A1h + kt * 4, bh);
            mma_bf16(D0 + nt * 4, A0l + kt * 4, bh);
            mma_bf16(D1 + nt * 4, A1l + kt * 4, bh);
            uint2 bl = bfL[(kt * 8 + nt) * 32 + lane];
            mma_bf16(D0 + nt * 4, A0h + kt * 4, bl);
            mma_bf16(D1 + nt * 4, A1h + kt * 4, bl);
        }
    }
}

// ---------------- kernel 0: init reduction buffers ----------------
__global__ __launch_bounds__(256) void init_kernel() {
    int i = blockIdx.x * blockDim.x + threadIdx.x;
    if (i < Nn * 16) {
        g_s4[i]   = make_float4(0.f, 0.f, 0.f, 0.f);
        g_acc4[i] = make_float4(0.f, 0.f, 0.f, 0.f);
    }
}

// ---------------- node helper: warp matmul over 2 nodes ----------------
__device__ __forceinline__ void mm2(const float2* __restrict__ Wf2,
                                    float i0a, float i0b, float i1a, float i1b,
                                    float2& o0, float2& o1) {
    const int lane = threadIdx.x & 31;
#pragma unroll
    for (int k = 0; k < 32; k++) {
        float v0 = __shfl_sync(0xffffffffu, i0a, k);
        float v1 = __shfl_sync(0xffffffffu, i1a, k);
        float2 wv = Wf2[k * 32 + lane];
        o0.x = fmaf(v0, wv.x, o0.x); o0.y = fmaf(v0, wv.y, o0.y);
        o1.x = fmaf(v1, wv.x, o1.x); o1.y = fmaf(v1, wv.y, o1.y);
    }
#pragma unroll
    for (int k = 0; k < 32; k++) {
        float v0 = __shfl_sync(0xffffffffu, i0b, k);
        float v1 = __shfl_sync(0xffffffffu, i1b, k);
        float2 wv = Wf2[(k + 32) * 32 + lane];
        o0.x = fmaf(v0, wv.x, o0.x); o0.y = fmaf(v0, wv.y, o0.y);
        o1.x = fmaf(v1, wv.x, o1.x); o1.y = fmaf(v1, wv.y, o1.y);
    }
}

// ---------------- kernel 1: node projections ----------------
__global__ __launch_bounds__(256) void node_proj_kernel(
    const float* __restrict__ x,
    const float* __restrict__ Win,  const float* __restrict__ bin,
    const float* __restrict__ Wlin, const float* __restrict__ Wsrc,
    const float* __restrict__ Wdst)
{
    extern __shared__ float smemf[];
    float2* sW = (float2*)smemf;
    float*  sb = smemf + 4 * 4096;
    int tid = threadIdx.x;
    for (int i = tid; i < 2048; i += 256) {
        int k = i >> 5, c = i & 31;
        sW[0 * 2048 + i] = make_float2(Win [k * 64 + c], Win [k * 64 + c + 32]);
        sW[1 * 2048 + i] = make_float2(Wlin[k * 64 + c], Wlin[k * 64 + c + 32]);
        sW[2 * 2048 + i] = make_float2(Wsrc[k * 64 + c], Wsrc[k * 64 + c + 32]);
        sW[3 * 2048 + i] = make_float2(Wdst[k * 64 + c], Wdst[k * 64 + c + 32]);
    }
    if (tid < 64) sb[tid] = bin[tid];
    __syncthreads();

    float* gv = (float*)g_v4;
    float* ga = (float*)g_as4;
    float* gd = (float*)g_ad4;

    int lane  = tid & 31;
    int warpG = blockIdx.x * 8 + (tid >> 5);
    int nW    = gridDim.x * 8;
    for (int p = warpG; p < Nn / 2; p += nW) {
        int n0 = 2 * p, n1 = n0 + 1;
        float x0a = x[n0 * 64 + lane], x0b = x[n0 * 64 + 32 + lane];
        float x1a = x[n1 * 64 + lane], x1b = x[n1 * 64 + 32 + lane];

        float2 h0 = make_float2(sb[lane], sb[lane + 32]);
        float2 h1 = h0;
        mm2(sW, x0a, x0b, x1a, x1b, h0, h1);
        h0.x = fmaxf(h0.x, 0.0f); h0.y = fmaxf(h0.y, 0.0f);
        h1.x = fmaxf(h1.x, 0.0f); h1.y = fmaxf(h1.y, 0.0f);

        float2 v0 = make_float2(0.f, 0.f), v1 = v0;
        mm2(sW + 1 * 2048, h0.x, h0.y, h1.x, h1.y, v0, v1);
        gv[n0 * 64 + lane] = v0.x; gv[n0 * 64 + 32 + lane] = v0.y;
        gv[n1 * 64 + lane] = v1.x; gv[n1 * 64 + 32 + lane] = v1.y;

        float2 s0 = make_float2(0.f, 0.f), s1 = s0;
        mm2(sW + 2 * 2048, h0.x, h0.y, h1.x, h1.y, s0, s1);
        ga[n0 * 64 + lane] = s0.x; ga[n0 * 64 + 32 + lane] = s0.y;
        ga[n1 * 64 + lane] = s1.x; ga[n1 * 64 + 32 + lane] = s1.y;

        float2 d0 = make_float2(0.f, 0.f), d1 = d0;
        mm2(sW + 3 * 2048, h0.x, h0.y, h1.x, h1.y, d0, d1);
        gd[n0 * 64 + lane] = d0.x; gd[n0 * 64 + 32 + lane] = d0.y;
        gd[n1 * 64 + lane] = d1.x; gd[n1 * 64 + 32 + lane] = d1.y;
    }
}

// ---------------- kernel 2: fused edge kernel (mma.sync bf16 split) ----------------
// smem (bytes):
//  [0, 49152)        B fragments: 6 variants (Wp2h,Wp2l,Wa1h,Wa1l,Wa2h,Wa2l)
//                    x [kt4][nt8][lane32] uint2
//  [49152, 114688)   delta scratch: 8 warps x 32 edges x 64 ch fp32
//  [114688, 115712)  Wp1 packed: float4[64] = {w0,w1,w2,bp1}[col]
//  [115712, 115968)  bp2 as float2[32]
//  [115968, 116224)  ba1 as float2[32]
//  [116224, 116480)  ba2 as float2[32]
//  [116480, 121600)  per-warp edge staging: 8 x (rel[32][3] + idx[32][2])
#define SM_BF    0
#define SM_DELTA 49152
#define SM_WP1   114688
#define SM_BP2   115712
#define SM_BA1   115968
#define SM_BA2   116224
#define SM_STAGE 116480
#define SM_TOTAL 121600

__global__ __launch_bounds__(256, 1) void edge_fused_kernel(
    const float* __restrict__ pos, const int* __restrict__ ei,
    const float* __restrict__ Wp1, const float* __restrict__ bp1,
    const float* __restrict__ Wp2, const float* __restrict__ bp2,
    const float* __restrict__ Wa1, const float* __restrict__ ba1,
    const float* __restrict__ Wa2, const float* __restrict__ ba2)
{
    extern __shared__ __align__(16) char smem[];
    uint2*  sBF   = (uint2*)(smem + SM_BF);
    float*  sDel  = (float*)(smem + SM_DELTA);
    float4* sWp1  = (float4*)(smem + SM_WP1);
    float2* sBp2  = (float2*)(smem + SM_BP2);
    float2* sBa1  = (float2*)(smem + SM_BA1);
    float2* sBa2  = (float2*)(smem + SM_BA2);
    float*  sStg  = (float*)(smem + SM_STAGE);

    const int tid = threadIdx.x;

    // ---- build B fragments (W row-major [k][n]; B frag: col=8nt+g, k rows) ----
    {
        const float* Wm[3] = { Wp2, Wa1, Wa2 };
#pragma unroll
        for (int m = 0; m < 3; m++) {
            const float* W = Wm[m];
            for (int i = tid; i < 1024; i += 256) {
                int kt = i >> 8, nt = (i >> 5) & 7, lane = i & 31;
                int g = lane >> 2, t = lane & 3;
                int col = 8 * nt + g;
                int k0  = 16 * kt + 2 * t;
                float w00 = W[(k0    ) * 64 + col];
                float w01 = W[(k0 + 1) * 64 + col];
                float w10 = W[(k0 + 8) * 64 + col];
                float w11 = W[(k0 + 9) * 64 + col];
                uint32_t h0, l0, h1, l1;
                pack_hl(w00, w01, h0, l0);
                pack_hl(w10, w11, h1, l1);
                int base = ((2 * m) * 4 + kt) * 8 + nt;
                sBF[base * 32 + lane]        = make_uint2(h0, h1);
                sBF[(base + 32) * 32 + lane] = make_uint2(l0, l1);  // lo variant (+4 kt-slots)
            }
        }
    }
    if (tid < 64)
        sWp1[tid] = make_float4(Wp1[tid], Wp1[64 + tid], Wp1[128 + tid], bp1[tid]);
    if (tid < 32) {
        sBp2[tid] = make_float2(bp2[2 * tid], bp2[2 * tid + 1]);
        sBa1[tid] = make_float2(ba1[2 * tid], ba1[2 * tid + 1]);
        sBa2[tid] = make_float2(ba2[2 * tid], ba2[2 * tid + 1]);
    }
    __syncthreads();

    const int lane = tid & 31;
    const int wic  = tid >> 5;            // warp in CTA
    const int g    = lane >> 2;
    const int t    = lane & 3;

    float* myDelta = sDel + wic * 2048;   // 32 edges x 64 ch
    float* swRel   = sStg + wic * 160;    // 96 rel + 64 idx(int)
    int*   swIdx   = (int*)(swRel + 96);

    const float* g_ad = (const float*)g_ad4;
    const float* g_as = (const float*)g_as4;
    const float* g_v  = (const float*)g_v4;

    const uint2* bfP2h = sBF + 0 * 1024;
    const uint2* bfP2l = sBF + 1 * 1024;
    const uint2* bfA1h = sBF + 2 * 1024;
    const uint2* bfA1l = sBF + 3 * 1024;
    const uint2* bfA2h = sBF + 4 * 1024;
    const uint2* bfA2l = sBF + 5 * 1024;

    const int nTiles = Ee / 32;           // 25000
    const int wStride = gridDim.x * 8;

    for (int tile = blockIdx.x * 8 + wic; tile < nTiles; tile += wStride) {
        const int e0 = tile * 32;

        // ---- stage edges: rel + indices into warp smem ----
        {
            int e  = e0 + lane;
            int s  = ei[e];
            int d  = ei[Ee + e];
            swIdx[lane * 2]     = s;
            swIdx[lane * 2 + 1] = d;
            swRel[lane * 3 + 0] = pos[d * 3 + 0] - pos[s * 3 + 0];
            swRel[lane * 3 + 1] = pos[d * 3 + 1] - pos[s * 3 + 1];
            swRel[lane * 3 + 2] = pos[d * 3 + 2] - pos[s * 3 + 2];
        }
        __syncwarp();

        int sn[4], dn[4];
        float rl[4][3];
#pragma unroll
        for (int h = 0; h < 4; h++) {
            int r = g + 8 * h;
            sn[h] = swIdx[r * 2];
            dn[h] = swIdx[r * 2 + 1];
            rl[h][0] = swRel[r * 3 + 0];
            rl[h][1] = swRel[r * 3 + 1];
            rl[h][2] = swRel[r * 3 + 2];
        }
        __syncwarp();

        // ---- stage 1: u = relu(rel @ Wp1 + bp1) directly in A-fragment layout ----
        uint32_t A0h[16], A0l[16], A1h[16], A1l[16];
#pragma unroll
        for (int kt = 0; kt < 4; kt++) {
#pragma unroll
            for (int half = 0; half < 2; half++) {
                int c0 = 16 * kt + 2 * t + 8 * half;
                float4 w0 = sWp1[c0];
                float4 w1 = sWp1[c0 + 1];
#pragma unroll
                for (int h = 0; h < 4; h++) {
                    float u0 = fmaxf(fmaf(rl[h][2], w0.z, fmaf(rl[h][1], w0.y,
                               fmaf(rl[h][0], w0.x, w0.w))), 0.f);
                    float u1 = fmaxf(fmaf(rl[h][2], w1.z, fmaf(rl[h][1], w1.y,
                               fmaf(rl[h][0], w1.x, w1.w))), 0.f);
                    uint32_t hw, lw;
                    pack_hl(u0, u1, hw, lw);
                    int slot = kt * 4 + (h & 1) + 2 * half;
                    if (h < 2) { A0h[slot] = hw; A0l[slot] = lw; }
                    else       { A1h[slot] = hw; A1l[slot] = lw; }
                }
            }
        }

        // ---- GEMM1: delta_raw = u @ Wp2 ----
        float D0[32], D1[32];
#pragma unroll
        for (int i = 0; i < 32; i++) { D0[i] = 0.f; D1[i] = 0.f; }
        gemm3p(D0, D1, A0h, A0l, A1h, A1l, bfP2h, bfP2l, lane);

        // ---- G1 epilogue: delta=D+bp2 (to smem); t=delta+ad[dn]-as[sn] → A frags ----
#pragma unroll
        for (int nt = 0; nt < 8; nt++) {
            int c0 = 8 * nt + 2 * t;
            float2 bb = sBp2[4 * nt + t];
            int kt = nt >> 1, half = nt & 1;
#pragma unroll
            for (int m = 0; m < 2; m++) {
                float* D = m ? D1 : D0;
                int h0 = 2 * m, h1 = 2 * m + 1;
                int r0 = g + 16 * m, r1 = r0 + 8;
                float d00 = D[nt * 4 + 0] + bb.x, d01 = D[nt * 4 + 1] + bb.y;
                float d10 = D[nt * 4 + 2] + bb.x, d11 = D[nt * 4 + 3] + bb.y;
                *(float2*)&myDelta[r0 * 64 + c0] = make_float2(d00, d01);
                *(float2*)&myDelta[r1 * 64 + c0] = make_float2(d10, d11);
                float2 ad0 = __ldg((const float2*)&g_ad[dn[h0] * 64 + c0]);
                float2 as0 = __ldg((const float2*)&g_as[sn[h0] * 64 + c0]);
                float2 ad1 = __ldg((const float2*)&g_ad[dn[h1] * 64 + c0]);
                float2 as1 = __ldg((const float2*)&g_as[sn[h1] * 64 + c0]);
                float t00 = d00 + ad0.x - as0.x, t01 = d01 + ad0.y - as0.y;
                float t10 = d10 + ad1.x - as1.x, t11 = d11 + ad1.y - as1.y;
                uint32_t hw, lw;
                int slot = kt * 4 + 2 * half;
                pack_hl(t00, t01, hw, lw);
                if (m == 0) { A0h[slot] = hw; A0l[slot] = lw; }
                else        { A1h[slot] = hw; A1l[slot] = lw; }
                pack_hl(t10, t11, hw, lw);
                if (m == 0) { A0h[slot + 1] = hw; A0l[slot + 1] = lw; }
                else        { A1h[slot + 1] = hw; A1l[slot + 1] = lw; }
            }
        }

        // ---- GEMM2: h2_raw = t @ Wa1 ----
#pragma unroll
        for (int i = 0; i < 32; i++) { D0[i] = 0.f; D1[i] = 0.f; }
        gemm3p(D0, D1, A0h, A0l, A1h, A1l, bfA1h, bfA1l, lane);

        // ---- G2 epilogue: h2 = relu(D + ba1) → A frags ----
#pragma unroll
        for (int nt = 0; nt < 8; nt++) {
            float2 bb = sBa1[4 * nt + t];
            int kt = nt >> 1, half = nt & 1;
#pragma unroll
            for (int m = 0; m < 2; m++) {
                float* D = m ? D1 : D0;
                float h00 = fmaxf(D[nt * 4 + 0] + bb.x, 0.f);
                float h01 = fmaxf(D[nt * 4 + 1] + bb.y, 0.f);
                float h10 = fmaxf(D[nt * 4 + 2] + bb.x, 0.f);
                float h11 = fmaxf(D[nt * 4 + 3] + bb.y, 0.f);
                uint32_t hw, lw;
                int slot = kt * 4 + 2 * half;
                pack_hl(h00, h01, hw, lw);
                if (m == 0) { A0h[slot] = hw; A0l[slot] = lw; }
                else        { A1h[slot] = hw; A1l[slot] = lw; }
                pack_hl(h10, h11, hw, lw);
                if (m == 0) { A0h[slot + 1] = hw; A0l[slot + 1] = lw; }
                else        { A1h[slot + 1] = hw; A1l[slot + 1] = lw; }
            }
        }

        // ---- GEMM3: logit_raw = h2 @ Wa2 ----
#pragma unroll
        for (int i = 0; i < 32; i++) { D0[i] = 0.f; D1[i] = 0.f; }
        gemm3p(D0, D1, A0h, A0l, A1h, A1l, bfA2h, bfA2l, lane);

        // ---- G3 epilogue: e = exp(D + ba2); scatter-add s and e*(v[sn]+delta) ----
#pragma unroll
        for (int nt = 0; nt < 8; nt++) {
            int c0 = 8 * nt + 2 * t;
            float2 bb = sBa2[4 * nt + t];
#pragma unroll
            for (int m = 0; m < 2; m++) {
                float* D = m ? D1 : D0;
                int h0 = 2 * m, h1 = 2 * m + 1;
                int r0 = g + 16 * m, r1 = r0 + 8;
                float e00 = __expf(D[nt * 4 + 0] + bb.x);
                float e01 = __expf(D[nt * 4 + 1] + bb.y);
                float e10 = __expf(D[nt * 4 + 2] + bb.x);
                float e11 = __expf(D[nt * 4 + 3] + bb.y);
                float2 dl0 = *(const float2*)&myDelta[r0 * 64 + c0];
                float2 dl1 = *(const float2*)&myDelta[r1 * 64 + c0];
                float2 v0 = __ldg((const float2*)&g_v[sn[h0] * 64 + c0]);
                float2 v1 = __ldg((const float2*)&g_v[sn[h1] * 64 + c0]);
                float a00 = e00 * (v0.x + dl0.x), a01 = e01 * (v0.y + dl0.y);
                float a10 = e10 * (v1.x + dl1.x), a11 = e11 * (v1.y + dl1.y);
                // merge lane pairs (t, t^1) -> float4 atomics on even t
                float pe0 = __shfl_xor_sync(0xffffffffu, e00, 1);
                float pe1 = __shfl_xor_sync(0xffffffffu, e01, 1);
                float pa0 = __shfl_xor_sync(0xffffffffu, a00, 1);
                float pa1 = __shfl_xor_sync(0xffffffffu, a01, 1);
                float qe0 = __shfl_xor_sync(0xffffffffu, e10, 1);
                float qe1 = __shfl_xor_sync(0xffffffffu, e11, 1);
                float qa0 = __shfl_xor_sync(0xffffffffu, a10, 1);
                float qa1 = __shfl_xor_sync(0xffffffffu, a11, 1);
                if ((t & 1) == 0) {
                    int fi = 2 * nt + (t >> 1);
                    red4(&g_s4  [dn[h0] * 16 + fi], e00, e01, pe0, pe1);
                    red4(&g_acc4[dn[h0] * 16 + fi], a00, a01, pa0, pa1);
                    red4(&g_s4  [dn[h1] * 16 + fi], e10, e11, qe0, qe1);
                    red4(&g_acc4[dn[h1] * 16 + fi], a10, a11, qa0, qa1);
                }
            }
        }
    }
}

// ---------------- kernel 3: normalize + lin_out + relu ----------------
__global__ __launch_bounds__(256) void node_out_kernel(
    const float* __restrict__ Wout, const float* __restrict__ bout,
    float* __restrict__ out)
{
    __shared__ float2 sW[2048];
    __shared__ float  sb[64];
    int tid = threadIdx.x;
    for (int i = tid; i < 2048; i += 256) {
        int k = i >> 5, c = i & 31;
        sW[i] = make_float2(Wout[k * 64 + c], Wout[k * 64 + c + 32]);
    }
    if (tid < 64) sb[tid] = bout[tid];
    __syncthreads();

    const float* gacc = (const float*)g_acc4;
    const float* gs   = (const float*)g_s4;

    int lane  = tid & 31;
    int warpG = blockIdx.x * 8 + (tid >> 5);
    int nW    = gridDim.x * 8;
    for (int p = warpG; p < Nn / 2; p += nW) {
        int n0 = 2 * p, n1 = n0 + 1;
        float r0a = gacc[n0 * 64 + lane]      / (gs[n0 * 64 + lane]      + 1e-16f);
        float r0b = gacc[n0 * 64 + 32 + lane] / (gs[n0 * 64 + 32 + lane] + 1e-16f);
        float r1a = gacc[n1 * 64 + lane]      / (gs[n1 * 64 + lane]      + 1e-16f);
        float r1b = gacc[n1 * 64 + 32 + lane] / (gs[n1 * 64 + 32 + lane] + 1e-16f);
        float2 o0 = make_float2(0.f, 0.f), o1 = o0;
        mm2(sW, r0a, r0b, r1a, r1b, o0, o1);
        out[n0 * 64 + lane]      = fmaxf(o0.x + sb[lane],      0.0f);
        out[n0 * 64 + 32 + lane] = fmaxf(o0.y + sb[lane + 32], 0.0f);
        out[n1 * 64 + lane]      = fmaxf(o1.x + sb[lane],      0.0f);
        out[n1 * 64 + 32 + lane] = fmaxf(o1.y + sb[lane + 32], 0.0f);
    }
}

// ---------------- launch ----------------
extern "C" void kernel_launch(void* const* d_in, const int* in_sizes, int n_in,
                              void* d_out, int out_size)
{
    const float* x    = (const float*)d_in[0];
    const float* pos  = (const float*)d_in[1];
    const int*   ei   = (const int*)  d_in[2];
    const float* Win  = (const float*)d_in[3];
    const float* bin  = (const float*)d_in[4];
    const float* Wlin = (const float*)d_in[5];
    const float* Wsrc = (const float*)d_in[6];
    const float* Wdst = (const float*)d_in[7];
    const float* Wp1  = (const float*)d_in[8];
    const float* bp1  = (const float*)d_in[9];
    const float* Wp2  = (const float*)d_in[10];
    const float* bp2  = (const float*)d_in[11];
    const float* Wa1  = (const float*)d_in[12];
    const float* ba1  = (const float*)d_in[13];
    const float* Wa2  = (const float*)d_in[14];
    const float* ba2  = (const float*)d_in[15];
    const float* Wout = (const float*)d_in[16];
    const float* bout = (const float*)d_in[17];

    const int nodeSmem = 4 * 16384 + 256;
    cudaFuncSetAttribute(node_proj_kernel,  cudaFuncAttributeMaxDynamicSharedMemorySize, nodeSmem);
    cudaFuncSetAttribute(edge_fused_kernel, cudaFuncAttributeMaxDynamicSharedMemorySize, SM_TOTAL);

    init_kernel<<<(Nn * 16 + 255) / 256, 256>>>();
    node_proj_kernel<<<444, 256, nodeSmem>>>(x, Win, bin, Wlin, Wsrc, Wdst);
    edge_fused_kernel<<<148, 256, SM_TOTAL>>>(pos, ei, Wp1, bp1, Wp2, bp2,
                                              Wa1, ba1, Wa2, ba2);
    node_out_kernel<<<592, 256>>>(Wout, bout, (float*)d_out);
}

// round 6
// speedup vs baseline: 5.5908x; 2.1045x over previous
#include <cuda_runtime.h>
#include <cuda_fp16.h>
#include <cstdint>
#include <cstddef>

#define Nn 50000
#define Ee 800000

// ---------------- scratch (static device globals; no allocation) ----------------
__device__ float4 g_v4  [Nn * 16];
__device__ float4 g_as4 [Nn * 16];
__device__ float4 g_ad4 [Nn * 16];
__device__ float4 g_s4  [Nn * 16];
__device__ float4 g_acc4[Nn * 16];

// ---------------- helpers ----------------
__device__ __forceinline__ uint32_t pack_f16x2(float a, float b) {
    uint32_t w;
    asm("cvt.rn.f16x2.f32 %0, %1, %2;" : "=r"(w) : "f"(b), "f"(a));  // lo=a, hi=b
    return w;
}
__device__ __forceinline__ void pack_hl_f16(float a, float b, uint32_t& h, uint32_t& l) {
    asm("cvt.rn.f16x2.f32 %0, %1, %2;" : "=r"(h) : "f"(b), "f"(a));
    __half2 h2 = *reinterpret_cast<__half2*>(&h);
    float la = a - __half2float(h2.x);
    float lb = b - __half2float(h2.y);
    asm("cvt.rn.f16x2.f32 %0, %1, %2;" : "=r"(l) : "f"(lb), "f"(la));
}
__device__ __forceinline__ void red4(float4* p, float a, float b, float c, float d) {
    asm volatile("red.global.add.v4.f32 [%0], {%1, %2, %3, %4};"
                 :: "l"(p), "f"(a), "f"(b), "f"(c), "f"(d) : "memory");
}

// m16n8k16 fp16 MMA, fp32 accumulate in-place
__device__ __forceinline__ void mma_f16(float* d, const uint32_t* a, uint2 b) {
    asm volatile(
        "mma.sync.aligned.m16n8k16.row.col.f32.f16.f16.f32 "
        "{%0,%1,%2,%3},{%4,%5,%6,%7},{%8,%9},{%0,%1,%2,%3};"
        : "+f"(d[0]), "+f"(d[1]), "+f"(d[2]), "+f"(d[3])
        : "r"(a[0]), "r"(a[1]), "r"(a[2]), "r"(a[3]), "r"(b.x), "r"(b.y));
}

// 16x64x64 GEMM, 2 products (A-hi x B-hi + A-hi x B-lo); D[32] = [nt8][4]
__device__ __forceinline__ void gemm2p(float* D, const uint32_t* Ah,
                                       const uint2* __restrict__ bfH,
                                       const uint2* __restrict__ bfL, int lane) {
#pragma unroll
    for (int kt = 0; kt < 4; kt++) {
#pragma unroll
        for (int nt = 0; nt < 8; nt++) {
            mma_f16(D + nt * 4, Ah + kt * 4, bfH[(kt * 8 + nt) * 32 + lane]);
            mma_f16(D + nt * 4, Ah + kt * 4, bfL[(kt * 8 + nt) * 32 + lane]);
        }
    }
}

// build B fragments for one 64x64 row-major W: hi at (2m)*1024, lo at (2m+1)*1024 (uint2 units)
__device__ __forceinline__ void build_bfrags(uint2* sBF, const float* __restrict__ W,
                                             int m, int tid, int nthreads) {
    for (int i = tid; i < 1024; i += nthreads) {
        int kt = i >> 8, nt = (i >> 5) & 7, lane = i & 31;
        int g = lane >> 2, t = lane & 3;
        int col = 8 * nt + g;
        int k0  = 16 * kt + 2 * t;
        float w00 = W[(k0    ) * 64 + col];
        float w01 = W[(k0 + 1) * 64 + col];
        float w10 = W[(k0 + 8) * 64 + col];
        float w11 = W[(k0 + 9) * 64 + col];
        uint32_t h0, l0, h1, l1;
        pack_hl_f16(w00, w01, h0, l0);
        pack_hl_f16(w10, w11, h1, l1);
        int base = ((2 * m) * 4 + kt) * 8 + nt;
        sBF[base * 32 + lane]        = make_uint2(h0, h1);
        sBF[(base + 32) * 32 + lane] = make_uint2(l0, l1);
    }
}

// ---------------- kernel 0: init reduction buffers ----------------
__global__ __launch_bounds__(256) void init_kernel() {
    int i = blockIdx.x * blockDim.x + threadIdx.x;
    if (i < Nn * 16) {
        g_s4[i]   = make_float4(0.f, 0.f, 0.f, 0.f);
        g_acc4[i] = make_float4(0.f, 0.f, 0.f, 0.f);
    }
}

// ---------------- kernel 1: node projections via mma ----------------
// smem: 8 B-frag arrays (Win h/l, Wlin h/l, Wsrc h/l, Wdst h/l) 8KB each + bin
__global__ __launch_bounds__(256) void node_proj_kernel(
    const float* __restrict__ x,
    const float* __restrict__ Win,  const float* __restrict__ bin,
    const float* __restrict__ Wlin, const float* __restrict__ Wsrc,
    const float* __restrict__ Wdst)
{
    extern __shared__ __align__(16) char smem[];
    uint2*  sBF  = (uint2*)smem;                       // 8 x 1024 uint2 = 64KB
    float2* sBin = (float2*)(smem + 65536);            // 32 float2
    const int tid = threadIdx.x;

    build_bfrags(sBF, Win,  0, tid, 256);
    build_bfrags(sBF, Wlin, 1, tid, 256);
    build_bfrags(sBF, Wsrc, 2, tid, 256);
    build_bfrags(sBF, Wdst, 3, tid, 256);
    if (tid < 32) sBin[tid] = make_float2(bin[2 * tid], bin[2 * tid + 1]);
    __syncthreads();

    const int lane = tid & 31;
    const int g = lane >> 2, t = lane & 3;
    const uint2* bfInH = sBF + 0 * 1024;
    const uint2* bfInL = sBF + 1 * 1024;
    const uint2* bfLnH = sBF + 2 * 1024;
    const uint2* bfLnL = sBF + 3 * 1024;
    const uint2* bfSrH = sBF + 4 * 1024;
    const uint2* bfSrL = sBF + 5 * 1024;
    const uint2* bfDsH = sBF + 6 * 1024;
    const uint2* bfDsL = sBF + 7 * 1024;

    float* gv = (float*)g_v4;
    float* ga = (float*)g_as4;
    float* gd = (float*)g_ad4;

    const int nTiles = Nn / 16;  // 3125
    const int wStride = gridDim.x * 8;
    for (int tile = blockIdx.x * 8 + (tid >> 5); tile < nTiles; tile += wStride) {
        const int n0 = tile * 16;

        // A frags from x (hi only)
        uint32_t Ah[16];
#pragma unroll
        for (int kt = 0; kt < 4; kt++)
#pragma unroll
            for (int half = 0; half < 2; half++)
#pragma unroll
                for (int h = 0; h < 2; h++) {
                    float2 xx = *(const float2*)&x[(n0 + g + 8 * h) * 64 + 16 * kt + 2 * t + 8 * half];
                    Ah[kt * 4 + h + 2 * half] = pack_f16x2(xx.x, xx.y);
                }

        // h = relu(x@Win + bin) -> Ah2 frags
        float D[32];
#pragma unroll
        for (int i = 0; i < 32; i++) D[i] = 0.f;
        gemm2p(D, Ah, bfInH, bfInL, lane);

        uint32_t Ah2[16];
#pragma unroll
        for (int nt = 0; nt < 8; nt++) {
            float2 bb = sBin[4 * nt + t];
            int kt = nt >> 1, half = nt & 1, slot = kt * 4 + 2 * half;
            float h00 = fmaxf(D[nt * 4 + 0] + bb.x, 0.f);
            float h01 = fmaxf(D[nt * 4 + 1] + bb.y, 0.f);
            float h10 = fmaxf(D[nt * 4 + 2] + bb.x, 0.f);
            float h11 = fmaxf(D[nt * 4 + 3] + bb.y, 0.f);
            Ah2[slot]     = pack_f16x2(h00, h01);
            Ah2[slot + 1] = pack_f16x2(h10, h11);
        }

        // v / a_src / a_dst
        float* outs[3] = { gv, ga, gd };
        const uint2* bh[3] = { bfLnH, bfSrH, bfDsH };
        const uint2* bl[3] = { bfLnL, bfSrL, bfDsL };
#pragma unroll
        for (int m = 0; m < 3; m++) {
#pragma unroll
            for (int i = 0; i < 32; i++) D[i] = 0.f;
            gemm2p(D, Ah2, bh[m], bl[m], lane);
            float* o = outs[m];
#pragma unroll
            for (int nt = 0; nt < 8; nt++) {
                int c0 = 8 * nt + 2 * t;
                *(float2*)&o[(n0 + g    ) * 64 + c0] = make_float2(D[nt * 4 + 0], D[nt * 4 + 1]);
                *(float2*)&o[(n0 + g + 8) * 64 + c0] = make_float2(D[nt * 4 + 2], D[nt * 4 + 3]);
            }
        }
    }
}

// ---------------- kernel 2: fused edge kernel (fp16 2-product mma) ----------------
// smem: [0,49152) 6 B-frag arrays (Wp2 h/l, Wa1 h/l, Wa2 h/l); then Wp1/biases/staging
#define SM_WP1   49152
#define SM_BP2   50176
#define SM_BA1   50432
#define SM_BA2   50688
#define SM_STAGE 50944
#define SM_TOTAL 53504

__global__ __launch_bounds__(256, 2) void edge_fused_kernel(
    const float* __restrict__ pos, const int* __restrict__ ei,
    const float* __restrict__ Wp1, const float* __restrict__ bp1,
    const float* __restrict__ Wp2, const float* __restrict__ bp2,
    const float* __restrict__ Wa1, const float* __restrict__ ba1,
    const float* __restrict__ Wa2, const float* __restrict__ ba2)
{
    extern __shared__ __align__(16) char smem[];
    uint2*  sBF  = (uint2*)smem;
    float4* sWp1 = (float4*)(smem + SM_WP1);
    float2* sBp2 = (float2*)(smem + SM_BP2);
    float2* sBa1 = (float2*)(smem + SM_BA1);
    float2* sBa2 = (float2*)(smem + SM_BA2);
    float*  sStg = (float*)(smem + SM_STAGE);

    const int tid = threadIdx.x;
    build_bfrags(sBF, Wp2, 0, tid, 256);
    build_bfrags(sBF, Wa1, 1, tid, 256);
    build_bfrags(sBF, Wa2, 2, tid, 256);
    if (tid < 64)
        sWp1[tid] = make_float4(Wp1[tid], Wp1[64 + tid], Wp1[128 + tid], bp1[tid]);
    if (tid < 32) {
        sBp2[tid] = make_float2(bp2[2 * tid], bp2[2 * tid + 1]);
        sBa1[tid] = make_float2(ba1[2 * tid], ba1[2 * tid + 1]);
        sBa2[tid] = make_float2(ba2[2 * tid], ba2[2 * tid + 1]);
    }
    __syncthreads();

    const int lane = tid & 31;
    const int wic  = tid >> 5;
    const int g = lane >> 2, t = lane & 3;

    float* swRel = sStg + wic * 80;     // 48 rel + 32 idx
    int*   swIdx = (int*)(swRel + 48);

    const float* g_ad = (const float*)g_ad4;
    const float* g_as = (const float*)g_as4;
    const float* g_v  = (const float*)g_v4;

    const uint2* bfP2h = sBF + 0 * 1024;
    const uint2* bfP2l = sBF + 1 * 1024;
    const uint2* bfA1h = sBF + 2 * 1024;
    const uint2* bfA1l = sBF + 3 * 1024;
    const uint2* bfA2h = sBF + 4 * 1024;
    const uint2* bfA2l = sBF + 5 * 1024;

    const int nTiles = Ee / 16;          // 50000
    const int wStride = gridDim.x * 8;

    for (int tile = blockIdx.x * 8 + wic; tile < nTiles; tile += wStride) {
        const int e0 = tile * 16;

        if (lane < 16) {
            int e = e0 + lane;
            int s = ei[e], d = ei[Ee + e];
            swIdx[lane * 2]     = s;
            swIdx[lane * 2 + 1] = d;
            swRel[lane * 3 + 0] = pos[d * 3 + 0] - pos[s * 3 + 0];
            swRel[lane * 3 + 1] = pos[d * 3 + 1] - pos[s * 3 + 1];
            swRel[lane * 3 + 2] = pos[d * 3 + 2] - pos[s * 3 + 2];
        }
        __syncwarp();

        int sn[2], dn[2];
        float rl[2][3];
#pragma unroll
        for (int h = 0; h < 2; h++) {
            int r = g + 8 * h;
            sn[h] = swIdx[r * 2];
            dn[h] = swIdx[r * 2 + 1];
            rl[h][0] = swRel[r * 3 + 0];
            rl[h][1] = swRel[r * 3 + 1];
            rl[h][2] = swRel[r * 3 + 2];
        }
        __syncwarp();

        // stage 1: u = relu(rel @ Wp1 + bp1) -> A frags (fp16 hi)
        uint32_t Ah[16];
#pragma unroll
        for (int kt = 0; kt < 4; kt++)
#pragma unroll
            for (int half = 0; half < 2; half++) {
                int c0 = 16 * kt + 2 * t + 8 * half;
                float4 w0 = sWp1[c0];
                float4 w1 = sWp1[c0 + 1];
#pragma unroll
                for (int h = 0; h < 2; h++) {
                    float u0 = fmaxf(fmaf(rl[h][2], w0.z, fmaf(rl[h][1], w0.y,
                               fmaf(rl[h][0], w0.x, w0.w))), 0.f);
                    float u1 = fmaxf(fmaf(rl[h][2], w1.z, fmaf(rl[h][1], w1.y,
                               fmaf(rl[h][0], w1.x, w1.w))), 0.f);
                    Ah[kt * 4 + h + 2 * half] = pack_f16x2(u0, u1);
                }
            }

        // GEMM1: delta_raw = u @ Wp2
        float D[32];
#pragma unroll
        for (int i = 0; i < 32; i++) D[i] = 0.f;
        gemm2p(D, Ah, bfP2h, bfP2l, lane);

        // G1 epilogue: delta = D+bp2 (regs); t = delta + ad[dn] - as[sn] -> A frags
        float dlt[32];
#pragma unroll
        for (int nt = 0; nt < 8; nt++) {
            int c0 = 8 * nt + 2 * t;
            float2 bb = sBp2[4 * nt + t];
            int kt = nt >> 1, half = nt & 1, slot = kt * 4 + 2 * half;
            float d00 = D[nt * 4 + 0] + bb.x, d01 = D[nt * 4 + 1] + bb.y;
            float d10 = D[nt * 4 + 2] + bb.x, d11 = D[nt * 4 + 3] + bb.y;
            dlt[nt * 4 + 0] = d00; dlt[nt * 4 + 1] = d01;
            dlt[nt * 4 + 2] = d10; dlt[nt * 4 + 3] = d11;
            float2 ad0 = __ldg((const float2*)&g_ad[dn[0] * 64 + c0]);
            float2 as0 = __ldg((const float2*)&g_as[sn[0] * 64 + c0]);
            float2 ad1 = __ldg((const float2*)&g_ad[dn[1] * 64 + c0]);
            float2 as1 = __ldg((const float2*)&g_as[sn[1] * 64 + c0]);
            Ah[slot]     = pack_f16x2(d00 + ad0.x - as0.x, d01 + ad0.y - as0.y);
            Ah[slot + 1] = pack_f16x2(d10 + ad1.x - as1.x, d11 + ad1.y - as1.y);
        }

        // GEMM2: h2_raw = t @ Wa1
#pragma unroll
        for (int i = 0; i < 32; i++) D[i] = 0.f;
        gemm2p(D, Ah, bfA1h, bfA1l, lane);

        // G2 epilogue: h2 = relu(D + ba1) -> A frags
#pragma unroll
        for (int nt = 0; nt < 8; nt++) {
            float2 bb = sBa1[4 * nt + t];
            int kt = nt >> 1, half = nt & 1, slot = kt * 4 + 2 * half;
            Ah[slot]     = pack_f16x2(fmaxf(D[nt * 4 + 0] + bb.x, 0.f),
                                      fmaxf(D[nt * 4 + 1] + bb.y, 0.f));
            Ah[slot + 1] = pack_f16x2(fmaxf(D[nt * 4 + 2] + bb.x, 0.f),
                                      fmaxf(D[nt * 4 + 3] + bb.y, 0.f));
        }

        // GEMM3: logit_raw = h2 @ Wa2
#pragma unroll
        for (int i = 0; i < 32; i++) D[i] = 0.f;
        gemm2p(D, Ah, bfA2h, bfA2l, lane);

        // G3 epilogue: e = exp(D + ba2); scatter-add s and e*(v[sn]+delta)
#pragma unroll
        for (int nt = 0; nt < 8; nt++) {
            int c0 = 8 * nt + 2 * t;
            float2 bb = sBa2[4 * nt + t];
            float e00 = __expf(D[nt * 4 + 0] + bb.x);
            float e01 = __expf(D[nt * 4 + 1] + bb.y);
            float e10 = __expf(D[nt * 4 + 2] + bb.x);
            float e11 = __expf(D[nt * 4 + 3] + bb.y);
            float2 v0 = __ldg((const float2*)&g_v[sn[0] * 64 + c0]);
            float2 v1 = __ldg((const float2*)&g_v[sn[1] * 64 + c0]);
            float a00 = e00 * (v0.x + dlt[nt * 4 + 0]);
            float a01 = e01 * (v0.y + dlt[nt * 4 + 1]);
            float a10 = e10 * (v1.x + dlt[nt * 4 + 2]);
            float a11 = e11 * (v1.y + dlt[nt * 4 + 3]);
            float pe0 = __shfl_xor_sync(0xffffffffu, e00, 1);
            float pe1 = __shfl_xor_sync(0xffffffffu, e01, 1);
            float pa0 = __shfl_xor_sync(0xffffffffu, a00, 1);
            float pa1 = __shfl_xor_sync(0xffffffffu, a01, 1);
            float qe0 = __shfl_xor_sync(0xffffffffu, e10, 1);
            float qe1 = __shfl_xor_sync(0xffffffffu, e11, 1);
            float qa0 = __shfl_xor_sync(0xffffffffu, a10, 1);
            float qa1 = __shfl_xor_sync(0xffffffffu, a11, 1);
            if ((t & 1) == 0) {
                int fi = 2 * nt + (t >> 1);
                red4(&g_s4  [dn[0] * 16 + fi], e00, e01, pe0, pe1);
                red4(&g_acc4[dn[0] * 16 + fi], a00, a01, pa0, pa1);
                red4(&g_s4  [dn[1] * 16 + fi], e10, e11, qe0, qe1);
                red4(&g_acc4[dn[1] * 16 + fi], a10, a11, qa0, qa1);
            }
        }
    }
}

// ---------------- node helper: warp matmul over 2 nodes ----------------
__device__ __forceinline__ void mm2(const float2* __restrict__ Wf2,
                                    float i0a, float i0b, float i1a, float i1b,
                                    float2& o0, float2& o1) {
    const int lane = threadIdx.x & 31;
#pragma unroll
    for (int k = 0; k < 32; k++) {
        float v0 = __shfl_sync(0xffffffffu, i0a, k);
        float v1 = __shfl_sync(0xffffffffu, i1a, k);
        float2 wv = Wf2[k * 32 + lane];
        o0.x = fmaf(v0, wv.x, o0.x); o0.y = fmaf(v0, wv.y, o0.y);
        o1.x = fmaf(v1, wv.x, o1.x); o1.y = fmaf(v1, wv.y, o1.y);
    }
#pragma unroll
    for (int k = 0; k < 32; k++) {
        float v0 = __shfl_sync(0xffffffffu, i0b, k);
        float v1 = __shfl_sync(0xffffffffu, i1b, k);
        float2 wv = Wf2[(k + 32) * 32 + lane];
        o0.x = fmaf(v0, wv.x, o0.x); o0.y = fmaf(v0, wv.y, o0.y);
        o1.x = fmaf(v1, wv.x, o1.x); o1.y = fmaf(v1, wv.y, o1.y);
    }
}

// ---------------- kernel 3: normalize + lin_out + relu ----------------
__global__ __launch_bounds__(256) void node_out_kernel(
    const float* __restrict__ Wout, const float* __restrict__ bout,
    float* __restrict__ out)
{
    __shared__ float2 sW[2048];
    __shared__ float  sb[64];
    int tid = threadIdx.x;
    for (int i = tid; i < 2048; i += 256) {
        int k = i >> 5, c = i & 31;
        sW[i] = make_float2(Wout[k * 64 + c], Wout[k * 64 + c + 32]);
    }
    if (tid < 64) sb[tid] = bout[tid];
    __syncthreads();

    const float* gacc = (const float*)g_acc4;
    const float* gs   = (const float*)g_s4;

    int lane  = tid & 31;
    int warpG = blockIdx.x * 8 + (tid >> 5);
    int nW    = gridDim.x * 8;
    for (int p = warpG; p < Nn / 2; p += nW) {
        int n0 = 2 * p, n1 = n0 + 1;
        float r0a = gacc[n0 * 64 + lane]      / (gs[n0 * 64 + lane]      + 1e-16f);
        float r0b = gacc[n0 * 64 + 32 + lane] / (gs[n0 * 64 + 32 + lane] + 1e-16f);
        float r1a = gacc[n1 * 64 + lane]      / (gs[n1 * 64 + lane]      + 1e-16f);
        float r1b = gacc[n1 * 64 + 32 + lane] / (gs[n1 * 64 + 32 + lane] + 1e-16f);
        float2 o0 = make_float2(0.f, 0.f), o1 = o0;
        mm2(sW, r0a, r0b, r1a, r1b, o0, o1);
        out[n0 * 64 + lane]      = fmaxf(o0.x + sb[lane],      0.0f);
        out[n0 * 64 + 32 + lane] = fmaxf(o0.y + sb[lane + 32], 0.0f);
        out[n1 * 64 + lane]      = fmaxf(o1.x + sb[lane],      0.0f);
        out[n1 * 64 + 32 + lane] = fmaxf(o1.y + sb[lane + 32], 0.0f);
    }
}

// ---------------- launch ----------------
extern "C" void kernel_launch(void* const* d_in, const int* in_sizes, int n_in,
                              void* d_out, int out_size)
{
    const float* x    = (const float*)d_in[0];
    const float* pos  = (const float*)d_in[1];
    const int*   ei   = (const int*)  d_in[2];
    const float* Win  = (const float*)d_in[3];
    const float* bin  = (const float*)d_in[4];
    const float* Wlin = (const float*)d_in[5];
    const float* Wsrc = (const float*)d_in[6];
    const float* Wdst = (const float*)d_in[7];
    const float* Wp1  = (const float*)d_in[8];
    const float* bp1  = (const float*)d_in[9];
    const float* Wp2  = (const float*)d_in[10];
    const float* bp2  = (const float*)d_in[11];
    const float* Wa1  = (const float*)d_in[12];
    const float* ba1  = (const float*)d_in[13];
    const float* Wa2  = (const float*)d_in[14];
    const float* ba2  = (const float*)d_in[15];
    const float* Wout = (const float*)d_in[16];
    const float* bout = (const float*)d_in[17];

    const int projSmem = 65536 + 256;
    cudaFuncSetAttribute(node_proj_kernel,  cudaFuncAttributeMaxDynamicSharedMemorySize, projSmem);
    cudaFuncSetAttribute(edge_fused_kernel, cudaFuncAttributeMaxDynamicSharedMemorySize, SM_TOTAL);

    init_kernel<<<(Nn * 16 + 255) / 256, 256>>>();
    node_proj_kernel<<<148, 256, projSmem>>>(x, Win, bin, Wlin, Wsrc, Wdst);
    edge_fused_kernel<<<296, 256, SM_TOTAL>>>(pos, ei, Wp1, bp1, Wp2, bp2,
                                              Wa1, ba1, Wa2, ba2);
    node_out_kernel<<<592, 256>>>(Wout, bout, (float*)d_out);
}

// round 7
// speedup vs baseline: 7.9786x; 1.4271x over previous
#include <cuda_runtime.h>
#include <cuda_fp16.h>
#include <cstdint>
#include <cstddef>

#define Nn 50000
#define Ee 800000

// ---------------- scratch (static device globals; no allocation) ----------------
// float accumulators (permuted channel layout p(c)=16t+2nt+j for c=8nt+2t+j)
__device__ float4 g_s4  [Nn * 16];
__device__ float4 g_acc4[Nn * 16];
// fp16 node operands, permuted layout
__device__ __align__(16) __half g_vh [Nn * 64];
__device__ __align__(16) __half g_ash[Nn * 64];
__device__ __align__(16) __half g_adh[Nn * 64];

// ---------------- helpers ----------------
__device__ __forceinline__ uint32_t pack_f16x2(float a, float b) {
    uint32_t w;
    asm("cvt.rn.f16x2.f32 %0, %1, %2;" : "=r"(w) : "f"(b), "f"(a));  // lo=a, hi=b
    return w;
}
__device__ __forceinline__ void pack_hl_f16(float a, float b, uint32_t& h, uint32_t& l) {
    asm("cvt.rn.f16x2.f32 %0, %1, %2;" : "=r"(h) : "f"(b), "f"(a));
    __half2 h2 = *reinterpret_cast<__half2*>(&h);
    float la = a - __half2float(h2.x);
    float lb = b - __half2float(h2.y);
    asm("cvt.rn.f16x2.f32 %0, %1, %2;" : "=r"(l) : "f"(lb), "f"(la));
}
__device__ __forceinline__ float2 h2f2(uint32_t w) {
    __half2 h = *reinterpret_cast<__half2*>(&w);
    return make_float2(__half2float(h.x), __half2float(h.y));
}
__device__ __forceinline__ void red4(float4* p, float a, float b, float c, float d) {
    asm volatile("red.global.add.v4.f32 [%0], {%1, %2, %3, %4};"
                 :: "l"(p), "f"(a), "f"(b), "f"(c), "f"(d) : "memory");
}
__device__ __forceinline__ void mma_f16(float* d, const uint32_t* a, uint2 b) {
    asm volatile(
        "mma.sync.aligned.m16n8k16.row.col.f32.f16.f16.f32 "
        "{%0,%1,%2,%3},{%4,%5,%6,%7},{%8,%9},{%0,%1,%2,%3};"
        : "+f"(d[0]), "+f"(d[1]), "+f"(d[2]), "+f"(d[3])
        : "r"(a[0]), "r"(a[1]), "r"(a[2]), "r"(a[3]), "r"(b.x), "r"(b.y));
}

__device__ __forceinline__ void gemm1p(float* D, const uint32_t* Ah,
                                       const uint2* __restrict__ bfH, int lane) {
#pragma unroll
    for (int kt = 0; kt < 4; kt++)
#pragma unroll
        for (int nt = 0; nt < 8; nt++)
            mma_f16(D + nt * 4, Ah + kt * 4, bfH[(kt * 8 + nt) * 32 + lane]);
}
__device__ __forceinline__ void gemm2p(float* D, const uint32_t* Ah,
                                       const uint2* __restrict__ bfH,
                                       const uint2* __restrict__ bfL, int lane) {
#pragma unroll
    for (int kt = 0; kt < 4; kt++)
#pragma unroll
        for (int nt = 0; nt < 8; nt++) {
            mma_f16(D + nt * 4, Ah + kt * 4, bfH[(kt * 8 + nt) * 32 + lane]);
            mma_f16(D + nt * 4, Ah + kt * 4, bfL[(kt * 8 + nt) * 32 + lane]);
        }
}
__device__ __forceinline__ void gemm3p(float* D, const uint32_t* Ah, const uint32_t* Al,
                                       const uint2* __restrict__ bfH,
                                       const uint2* __restrict__ bfL, int lane) {
#pragma unroll
    for (int kt = 0; kt < 4; kt++)
#pragma unroll
        for (int nt = 0; nt < 8; nt++) {
            uint2 bh = bfH[(kt * 8 + nt) * 32 + lane];
            mma_f16(D + nt * 4, Ah + kt * 4, bh);
            mma_f16(D + nt * 4, Al + kt * 4, bh);
            mma_f16(D + nt * 4, Ah + kt * 4, bfL[(kt * 8 + nt) * 32 + lane]);
        }
}

// build B fragments from 64x64 row-major W (logical indices); dstL may be null
__device__ __forceinline__ void build_bf(uint2* dstH, uint2* dstL,
                                         const float* __restrict__ W,
                                         int tid, int nth) {
    for (int i = tid; i < 1024; i += nth) {
        int kt = i >> 8, nt = (i >> 5) & 7, lane = i & 31;
        int g = lane >> 2, t = lane & 3;
        int col = 8 * nt + g;
        int k0  = 16 * kt + 2 * t;
        float w00 = W[(k0    ) * 64 + col];
        float w01 = W[(k0 + 1) * 64 + col];
        float w10 = W[(k0 + 8) * 64 + col];
        float w11 = W[(k0 + 9) * 64 + col];
        uint32_t h0, l0, h1, l1;
        pack_hl_f16(w00, w01, h0, l0);
        pack_hl_f16(w10, w11, h1, l1);
        int idx = (kt * 8 + nt) * 32 + lane;
        dstH[idx] = make_uint2(h0, h1);
        if (dstL) dstL[idx] = make_uint2(l0, l1);
    }
}

// ---------------- kernel 0: init reduction buffers ----------------
__global__ __launch_bounds__(256) void init_kernel() {
    int i = blockIdx.x * blockDim.x + threadIdx.x;
    if (i < Nn * 16) {
        g_s4[i]   = make_float4(0.f, 0.f, 0.f, 0.f);
        g_acc4[i] = make_float4(0.f, 0.f, 0.f, 0.f);
    }
}

// ---------------- kernel 1: node projections (mma, fp16 permuted outputs) ----------------
__global__ __launch_bounds__(256) void node_proj_kernel(
    const float* __restrict__ x,
    const float* __restrict__ Win,  const float* __restrict__ bin,
    const float* __restrict__ Wlin, const float* __restrict__ Wsrc,
    const float* __restrict__ Wdst)
{
    extern __shared__ __align__(16) char smem[];
    uint2*  sBF  = (uint2*)smem;                       // 8 x 1024 uint2 = 64KB
    float2* sBin = (float2*)(smem + 65536);
    const int tid = threadIdx.x;

    build_bf(sBF + 0 * 1024, sBF + 1 * 1024, Win,  tid, 256);
    build_bf(sBF + 2 * 1024, sBF + 3 * 1024, Wlin, tid, 256);
    build_bf(sBF + 4 * 1024, sBF + 5 * 1024, Wsrc, tid, 256);
    build_bf(sBF + 6 * 1024, sBF + 7 * 1024, Wdst, tid, 256);
    if (tid < 32) sBin[tid] = make_float2(bin[2 * tid], bin[2 * tid + 1]);
    __syncthreads();

    const int lane = tid & 31;
    const int g = lane >> 2, t = lane & 3;

    __half* outs[3] = { g_vh, g_ash, g_adh };

    const int nTiles = Nn / 16;  // 3125
    const int wStride = gridDim.x * 8;
    for (int tile = blockIdx.x * 8 + (tid >> 5); tile < nTiles; tile += wStride) {
        const int n0 = tile * 16;

        uint32_t Ah[16];
#pragma unroll
        for (int kt = 0; kt < 4; kt++)
#pragma unroll
            for (int half = 0; half < 2; half++)
#pragma unroll
                for (int h = 0; h < 2; h++) {
                    float2 xx = *(const float2*)&x[(n0 + g + 8 * h) * 64 + 16 * kt + 2 * t + 8 * half];
                    Ah[kt * 4 + h + 2 * half] = pack_f16x2(xx.x, xx.y);
                }

        float D[32];
#pragma unroll
        for (int i = 0; i < 32; i++) D[i] = 0.f;
        gemm2p(D, Ah, sBF + 0 * 1024, sBF + 1 * 1024, lane);

        uint32_t Ah2[16];
#pragma unroll
        for (int nt = 0; nt < 8; nt++) {
            float2 bb = sBin[4 * nt + t];
            int kt = nt >> 1, half = nt & 1, slot = kt * 4 + 2 * half;
            Ah2[slot]     = pack_f16x2(fmaxf(D[nt * 4 + 0] + bb.x, 0.f),
                                       fmaxf(D[nt * 4 + 1] + bb.y, 0.f));
            Ah2[slot + 1] = pack_f16x2(fmaxf(D[nt * 4 + 2] + bb.x, 0.f),
                                       fmaxf(D[nt * 4 + 3] + bb.y, 0.f));
        }

#pragma unroll
        for (int m = 0; m < 3; m++) {
#pragma unroll
            for (int i = 0; i < 32; i++) D[i] = 0.f;
            gemm2p(D, Ah2, sBF + (2 + 2 * m) * 1024, sBF + (3 + 2 * m) * 1024, lane);
            __half* o = outs[m];
            // permuted fp16 store: channel 8nt+2t+j -> storage 16t+2nt+j
#pragma unroll
            for (int ntp = 0; ntp < 4; ntp++) {
                int na = 2 * ntp, nb = na + 1;
                uint2 r0 = make_uint2(pack_f16x2(D[na * 4 + 0], D[na * 4 + 1]),
                                      pack_f16x2(D[nb * 4 + 0], D[nb * 4 + 1]));
                uint2 r8 = make_uint2(pack_f16x2(D[na * 4 + 2], D[na * 4 + 3]),
                                      pack_f16x2(D[nb * 4 + 2], D[nb * 4 + 3]));
                *(uint2*)(o + (n0 + g    ) * 64 + 16 * t + 4 * ntp) = r0;
                *(uint2*)(o + (n0 + g + 8) * 64 + 16 * t + 4 * ntp) = r8;
            }
        }
    }
}

// ---------------- kernel 2: fused edge kernel ----------------
// smem: [0,32768) 4 B-frag arrays (Wp2 h, Wp2 l, Wa1 h, Wa2 h)
#define ESM_WP1   32768
#define ESM_BP2   33792
#define ESM_BA1   34048
#define ESM_BA2   34304
#define ESM_STAGE 34560
#define ESM_TOTAL 37120

__global__ __launch_bounds__(256, 2) void edge_fused_kernel(
    const float* __restrict__ pos, const int* __restrict__ ei,
    const float* __restrict__ Wp1, const float* __restrict__ bp1,
    const float* __restrict__ Wp2, const float* __restrict__ bp2,
    const float* __restrict__ Wa1, const float* __restrict__ ba1,
    const float* __restrict__ Wa2, const float* __restrict__ ba2)
{
    extern __shared__ __align__(16) char smem[];
    uint2*  sBF  = (uint2*)smem;
    float4* sWp1 = (float4*)(smem + ESM_WP1);
    float2* sBp2 = (float2*)(smem + ESM_BP2);
    float2* sBa1 = (float2*)(smem + ESM_BA1);
    float2* sBa2 = (float2*)(smem + ESM_BA2);
    float*  sStg = (float*)(smem + ESM_STAGE);

    const int tid = threadIdx.x;
    build_bf(sBF + 0 * 1024, sBF + 1 * 1024, Wp2, tid, 256);
    build_bf(sBF + 2 * 1024, (uint2*)0,      Wa1, tid, 256);
    build_bf(sBF + 3 * 1024, (uint2*)0,      Wa2, tid, 256);
    if (tid < 64)
        sWp1[tid] = make_float4(Wp1[tid], Wp1[64 + tid], Wp1[128 + tid], bp1[tid]);
    if (tid < 32) {
        sBp2[tid] = make_float2(bp2[2 * tid], bp2[2 * tid + 1]);
        sBa1[tid] = make_float2(ba1[2 * tid], ba1[2 * tid + 1]);
        sBa2[tid] = make_float2(ba2[2 * tid], ba2[2 * tid + 1]);
    }
    __syncthreads();

    const int lane = tid & 31;
    const int wic  = tid >> 5;
    const int g = lane >> 2, t = lane & 3;

    float* swRel = sStg + wic * 80;
    int*   swIdx = (int*)(swRel + 48);

    const uint2* bfP2h = sBF + 0 * 1024;
    const uint2* bfP2l = sBF + 1 * 1024;
    const uint2* bfA1h = sBF + 2 * 1024;
    const uint2* bfA2h = sBF + 3 * 1024;

    const int nTiles = Ee / 16;          // 50000
    const int wStride = gridDim.x * 8;

    for (int tile = blockIdx.x * 8 + wic; tile < nTiles; tile += wStride) {
        const int e0 = tile * 16;

        if (lane < 16) {
            int e = e0 + lane;
            int s = ei[e], d = ei[Ee + e];
            swIdx[lane * 2]     = s;
            swIdx[lane * 2 + 1] = d;
            swRel[lane * 3 + 0] = pos[d * 3 + 0] - pos[s * 3 + 0];
            swRel[lane * 3 + 1] = pos[d * 3 + 1] - pos[s * 3 + 1];
            swRel[lane * 3 + 2] = pos[d * 3 + 2] - pos[s * 3 + 2];
        }
        __syncwarp();

        int sn[2], dn[2];
        float rl[2][3];
#pragma unroll
        for (int h = 0; h < 2; h++) {
            int r = g + 8 * h;
            sn[h] = swIdx[r * 2];
            dn[h] = swIdx[r * 2 + 1];
            rl[h][0] = swRel[r * 3 + 0];
            rl[h][1] = swRel[r * 3 + 1];
            rl[h][2] = swRel[r * 3 + 2];
        }
        __syncwarp();

        // stage 1: u = relu(rel @ Wp1 + bp1) -> A frags
        uint32_t Ah[16];
#pragma unroll
        for (int kt = 0; kt < 4; kt++)
#pragma unroll
            for (int half = 0; half < 2; half++) {
                int c0 = 16 * kt + 2 * t + 8 * half;
                float4 w0 = sWp1[c0];
                float4 w1 = sWp1[c0 + 1];
#pragma unroll
                for (int h = 0; h < 2; h++) {
                    float u0 = fmaxf(fmaf(rl[h][2], w0.z, fmaf(rl[h][1], w0.y,
                               fmaf(rl[h][0], w0.x, w0.w))), 0.f);
                    float u1 = fmaxf(fmaf(rl[h][2], w1.z, fmaf(rl[h][1], w1.y,
                               fmaf(rl[h][0], w1.x, w1.w))), 0.f);
                    Ah[kt * 4 + h + 2 * half] = pack_f16x2(u0, u1);
                }
            }

        // GEMM1: delta_raw = u @ Wp2 (2-product)
        float D[32];
#pragma unroll
        for (int i = 0; i < 32; i++) D[i] = 0.f;
        gemm2p(D, Ah, bfP2h, bfP2l, lane);

        // gathers: each thread's 16 channels are contiguous in permuted storage
        uint32_t wad0[8], was0[8], wad1[8], was1[8];
        {
            const uint4* p;
            uint4 a, b;
            p = (const uint4*)(g_adh + dn[0] * 64 + 16 * t); a = p[0]; b = p[1];
            wad0[0]=a.x; wad0[1]=a.y; wad0[2]=a.z; wad0[3]=a.w;
            wad0[4]=b.x; wad0[5]=b.y; wad0[6]=b.z; wad0[7]=b.w;
            p = (const uint4*)(g_ash + sn[0] * 64 + 16 * t); a = p[0]; b = p[1];
            was0[0]=a.x; was0[1]=a.y; was0[2]=a.z; was0[3]=a.w;
            was0[4]=b.x; was0[5]=b.y; was0[6]=b.z; was0[7]=b.w;
            p = (const uint4*)(g_adh + dn[1] * 64 + 16 * t); a = p[0]; b = p[1];
            wad1[0]=a.x; wad1[1]=a.y; wad1[2]=a.z; wad1[3]=a.w;
            wad1[4]=b.x; wad1[5]=b.y; wad1[6]=b.z; wad1[7]=b.w;
            p = (const uint4*)(g_ash + sn[1] * 64 + 16 * t); a = p[0]; b = p[1];
            was1[0]=a.x; was1[1]=a.y; was1[2]=a.z; was1[3]=a.w;
            was1[4]=b.x; was1[5]=b.y; was1[6]=b.z; was1[7]=b.w;
        }

        // G1 epilogue: delta = D + bp2 (regs); t = delta + ad[dn] - as[sn] -> A frags
        float dlt[32];
#pragma unroll
        for (int nt = 0; nt < 8; nt++) {
            float2 bb = sBp2[4 * nt + t];
            int kt = nt >> 1, half = nt & 1, slot = kt * 4 + 2 * half;
            float d00 = D[nt * 4 + 0] + bb.x, d01 = D[nt * 4 + 1] + bb.y;
            float d10 = D[nt * 4 + 2] + bb.x, d11 = D[nt * 4 + 3] + bb.y;
            dlt[nt * 4 + 0] = d00; dlt[nt * 4 + 1] = d01;
            dlt[nt * 4 + 2] = d10; dlt[nt * 4 + 3] = d11;
            float2 ad0 = h2f2(wad0[nt]), as0 = h2f2(was0[nt]);
            float2 ad1 = h2f2(wad1[nt]), as1 = h2f2(was1[nt]);
            Ah[slot]     = pack_f16x2(d00 + ad0.x - as0.x, d01 + ad0.y - as0.y);
            Ah[slot + 1] = pack_f16x2(d10 + ad1.x - as1.x, d11 + ad1.y - as1.y);
        }

        // GEMM2: h2_raw = t @ Wa1 (1-product)
#pragma unroll
        for (int i = 0; i < 32; i++) D[i] = 0.f;
        gemm1p(D, Ah, bfA1h, lane);

        // G2 epilogue: h2 = relu(D + ba1)
#pragma unroll
        for (int nt = 0; nt < 8; nt++) {
            float2 bb = sBa1[4 * nt + t];
            int kt = nt >> 1, half = nt & 1, slot = kt * 4 + 2 * half;
            Ah[slot]     = pack_f16x2(fmaxf(D[nt * 4 + 0] + bb.x, 0.f),
                                      fmaxf(D[nt * 4 + 1] + bb.y, 0.f));
            Ah[slot + 1] = pack_f16x2(fmaxf(D[nt * 4 + 2] + bb.x, 0.f),
                                      fmaxf(D[nt * 4 + 3] + bb.y, 0.f));
        }

        // GEMM3: logit_raw = h2 @ Wa2 (1-product)
#pragma unroll
        for (int i = 0; i < 32; i++) D[i] = 0.f;
        gemm1p(D, Ah, bfA2h, lane);

        // v gathers
        uint32_t wv0[8], wv1[8];
        {
            const uint4* p;
            uint4 a, b;
            p = (const uint4*)(g_vh + sn[0] * 64 + 16 * t); a = p[0]; b = p[1];
            wv0[0]=a.x; wv0[1]=a.y; wv0[2]=a.z; wv0[3]=a.w;
            wv0[4]=b.x; wv0[5]=b.y; wv0[6]=b.z; wv0[7]=b.w;
            p = (const uint4*)(g_vh + sn[1] * 64 + 16 * t); a = p[0]; b = p[1];
            wv1[0]=a.x; wv1[1]=a.y; wv1[2]=a.z; wv1[3]=a.w;
            wv1[4]=b.x; wv1[5]=b.y; wv1[6]=b.z; wv1[7]=b.w;
        }

        // G3 epilogue: per nt-pair, thread-local contiguous float4 reductions
        float* sp = (float*)g_s4;
        float* ap = (float*)g_acc4;
#pragma unroll
        for (int ntp = 0; ntp < 4; ntp++) {
            int na = 2 * ntp, nb = na + 1;
            float2 ba_a = sBa2[4 * na + t], ba_b = sBa2[4 * nb + t];
            float2 va0 = h2f2(wv0[na]), vb0 = h2f2(wv0[nb]);
            float2 va1 = h2f2(wv1[na]), vb1 = h2f2(wv1[nb]);
            // edge 0 (row g)
            float e00 = __expf(D[na * 4 + 0] + ba_a.x);
            float e01 = __expf(D[na * 4 + 1] + ba_a.y);
            float e02 = __expf(D[nb * 4 + 0] + ba_b.x);
            float e03 = __expf(D[nb * 4 + 1] + ba_b.y);
            float a00 = e00 * (va0.x + dlt[na * 4 + 0]);
            float a01 = e01 * (va0.y + dlt[na * 4 + 1]);
            float a02 = e02 * (vb0.x + dlt[nb * 4 + 0]);
            float a03 = e03 * (vb0.y + dlt[nb * 4 + 1]);
            int off0 = dn[0] * 64 + 16 * t + 4 * ntp;
            red4((float4*)(sp + off0), e00, e01, e02, e03);
            red4((float4*)(ap + off0), a00, a01, a02, a03);
            // edge 1 (row g+8)
            float e10 = __expf(D[na * 4 + 2] + ba_a.x);
            float e11 = __expf(D[na * 4 + 3] + ba_a.y);
            float e12 = __expf(D[nb * 4 + 2] + ba_b.x);
            float e13 = __expf(D[nb * 4 + 3] + ba_b.y);
            float a10 = e10 * (va1.x + dlt[na * 4 + 2]);
            float a11 = e11 * (va1.y + dlt[na * 4 + 3]);
            float a12 = e12 * (vb1.x + dlt[nb * 4 + 2]);
            float a13 = e13 * (vb1.y + dlt[nb * 4 + 3]);
            int off1 = dn[1] * 64 + 16 * t + 4 * ntp;
            red4((float4*)(sp + off1), e10, e11, e12, e13);
            red4((float4*)(ap + off1), a10, a11, a12, a13);
        }
    }
}

// ---------------- kernel 3: normalize + lin_out + relu (mma) ----------------
__global__ __launch_bounds__(256) void node_out_kernel(
    const float* __restrict__ Wout, const float* __restrict__ bout,
    float* __restrict__ out)
{
    extern __shared__ __align__(16) char smem[];
    uint2*  sBF  = (uint2*)smem;                  // Wout hi + lo = 16KB
    float2* sB   = (float2*)(smem + 16384);
    const int tid = threadIdx.x;
    build_bf(sBF, sBF + 1024, Wout, tid, 256);
    if (tid < 32) sB[tid] = make_float2(bout[2 * tid], bout[2 * tid + 1]);
    __syncthreads();

    const int lane = tid & 31;
    const int g = lane >> 2, t = lane & 3;
    const float* accp = (const float*)g_acc4;
    const float* ssp  = (const float*)g_s4;

    const int nTiles = Nn / 16;  // 3125
    const int wStride = gridDim.x * 8;
    for (int tile = blockIdx.x * 8 + (tid >> 5); tile < nTiles; tile += wStride) {
        const int n0 = tile * 16;

        // gather permuted acc/s: contiguous 16 floats per thread per row
        float rg0[16], rg1[16];
#pragma unroll
        for (int q = 0; q < 4; q++) {
            float4 a0 = *(const float4*)(accp + (n0 + g) * 64 + 16 * t + 4 * q);
            float4 s0 = *(const float4*)(ssp  + (n0 + g) * 64 + 16 * t + 4 * q);
            rg0[4 * q + 0] = a0.x / (s0.x + 1e-16f);
            rg0[4 * q + 1] = a0.y / (s0.y + 1e-16f);
            rg0[4 * q + 2] = a0.z / (s0.z + 1e-16f);
            rg0[4 * q + 3] = a0.w / (s0.w + 1e-16f);
            float4 a1 = *(const float4*)(accp + (n0 + g + 8) * 64 + 16 * t + 4 * q);
            float4 s1 = *(const float4*)(ssp  + (n0 + g + 8) * 64 + 16 * t + 4 * q);
            rg1[4 * q + 0] = a1.x / (s1.x + 1e-16f);
            rg1[4 * q + 1] = a1.y / (s1.y + 1e-16f);
            rg1[4 * q + 2] = a1.z / (s1.z + 1e-16f);
            rg1[4 * q + 3] = a1.w / (s1.w + 1e-16f);
        }

        uint32_t Ah[16], Al[16];
#pragma unroll
        for (int nt = 0; nt < 8; nt++) {
            int kt = nt >> 1, half = nt & 1, slot = kt * 4 + 2 * half;
            pack_hl_f16(rg0[2 * nt], rg0[2 * nt + 1], Ah[slot],     Al[slot]);
            pack_hl_f16(rg1[2 * nt], rg1[2 * nt + 1], Ah[slot + 1], Al[slot + 1]);
        }

        float D[32];
#pragma unroll
        for (int i = 0; i < 32; i++) D[i] = 0.f;
        gemm3p(D, Ah, Al, sBF, sBF + 1024, lane);

#pragma unroll
        for (int nt = 0; nt < 8; nt++) {
            int c0 = 8 * nt + 2 * t;
            float2 bb = sB[4 * nt + t];
            *(float2*)&out[(n0 + g    ) * 64 + c0] =
                make_float2(fmaxf(D[nt * 4 + 0] + bb.x, 0.f),
                            fmaxf(D[nt * 4 + 1] + bb.y, 0.f));
            *(float2*)&out[(n0 + g + 8) * 64 + c0] =
                make_float2(fmaxf(D[nt * 4 + 2] + bb.x, 0.f),
                            fmaxf(D[nt * 4 + 3] + bb.y, 0.f));
        }
    }
}

// ---------------- launch ----------------
extern "C" void kernel_launch(void* const* d_in, const int* in_sizes, int n_in,
                              void* d_out, int out_size)
{
    const float* x    = (const float*)d_in[0];
    const float* pos  = (const float*)d_in[1];
    const int*   ei   = (const int*)  d_in[2];
    const float* Win  = (const float*)d_in[3];
    const float* bin  = (const float*)d_in[4];
    const float* Wlin = (const float*)d_in[5];
    const float* Wsrc = (const float*)d_in[6];
    const float* Wdst = (const float*)d_in[7];
    const float* Wp1  = (const float*)d_in[8];
    const float* bp1  = (const float*)d_in[9];
    const float* Wp2  = (const float*)d_in[10];
    const float* bp2  = (const float*)d_in[11];
    const float* Wa1  = (const float*)d_in[12];
    const float* ba1  = (const float*)d_in[13];
    const float* Wa2  = (const float*)d_in[14];
    const float* ba2  = (const float*)d_in[15];
    const float* Wout = (const float*)d_in[16];
    const float* bout = (const float*)d_in[17];

    const int projSmem = 65536 + 256;
    const int outSmem  = 16384 + 256;
    cudaFuncSetAttribute(node_proj_kernel,  cudaFuncAttributeMaxDynamicSharedMemorySize, projSmem);
    cudaFuncSetAttribute(edge_fused_kernel, cudaFuncAttributeMaxDynamicSharedMemorySize, ESM_TOTAL);
    cudaFuncSetAttribute(node_out_kernel,   cudaFuncAttributeMaxDynamicSharedMemorySize, outSmem);

    init_kernel<<<(Nn * 16 + 255) / 256, 256>>>();
    node_proj_kernel<<<148, 256, projSmem>>>(x, Win, bin, Wlin, Wsrc, Wdst);
    edge_fused_kernel<<<296, 256, ESM_TOTAL>>>(pos, ei, Wp1, bp1, Wp2, bp2,
                                               Wa1, ba1, Wa2, ba2);
    node_out_kernel<<<148, 256, outSmem>>>(Wout, bout, (float*)d_out);
}

// round 8
// speedup vs baseline: 8.3849x; 1.0509x over previous
#include <cuda_runtime.h>
#include <cuda_fp16.h>
#include <cstdint>
#include <cstddef>

#define Nn 50000
#define Ee 800000

// ---------------- scratch (static device globals; no allocation) ----------------
// float accumulators (permuted channel layout p(c)=16t+2nt+j for c=8nt+2t+j)
__device__ float4 g_s4  [Nn * 16];
__device__ float4 g_acc4[Nn * 16];
// fp16 node operands, permuted layout
__device__ __align__(16) __half g_vh [Nn * 64];
__device__ __align__(16) __half g_ash[Nn * 64];
__device__ __align__(16) __half g_adh[Nn * 64];

// ---------------- helpers ----------------
__device__ __forceinline__ uint32_t pack_f16x2(float a, float b) {
    uint32_t w;
    asm("cvt.rn.f16x2.f32 %0, %1, %2;" : "=r"(w) : "f"(b), "f"(a));  // lo=a, hi=b
    return w;
}
__device__ __forceinline__ void pack_hl_f16(float a, float b, uint32_t& h, uint32_t& l) {
    asm("cvt.rn.f16x2.f32 %0, %1, %2;" : "=r"(h) : "f"(b), "f"(a));
    __half2 h2 = *reinterpret_cast<__half2*>(&h);
    float la = a - __half2float(h2.x);
    float lb = b - __half2float(h2.y);
    asm("cvt.rn.f16x2.f32 %0, %1, %2;" : "=r"(l) : "f"(lb), "f"(la));
}
__device__ __forceinline__ float2 h2f2(uint32_t w) {
    __half2 h = *reinterpret_cast<__half2*>(&w);
    return make_float2(__half2float(h.x), __half2float(h.y));
}
__device__ __forceinline__ void red4(float4* p, float a, float b, float c, float d) {
    asm volatile("red.global.add.v4.f32 [%0], {%1, %2, %3, %4};"
                 :: "l"(p), "f"(a), "f"(b), "f"(c), "f"(d) : "memory");
}
__device__ __forceinline__ void mma_f16(float* d, const uint32_t* a, uint2 b) {
    asm volatile(
        "mma.sync.aligned.m16n8k16.row.col.f32.f16.f16.f32 "
        "{%0,%1,%2,%3},{%4,%5,%6,%7},{%8,%9},{%0,%1,%2,%3};"
        : "+f"(d[0]), "+f"(d[1]), "+f"(d[2]), "+f"(d[3])
        : "r"(a[0]), "r"(a[1]), "r"(a[2]), "r"(a[3]), "r"(b.x), "r"(b.y));
}
__device__ __forceinline__ void gemm1p(float* D, const uint32_t* Ah,
                                       const uint2* __restrict__ bfH, int lane) {
#pragma unroll
    for (int kt = 0; kt < 4; kt++)
#pragma unroll
        for (int nt = 0; nt < 8; nt++)
            mma_f16(D + nt * 4, Ah + kt * 4, bfH[(kt * 8 + nt) * 32 + lane]);
}
__device__ __forceinline__ void gemm2p(float* D, const uint32_t* Ah,
                                       const uint2* __restrict__ bfH,
                                       const uint2* __restrict__ bfL, int lane) {
#pragma unroll
    for (int kt = 0; kt < 4; kt++)
#pragma unroll
        for (int nt = 0; nt < 8; nt++) {
            mma_f16(D + nt * 4, Ah + kt * 4, bfH[(kt * 8 + nt) * 32 + lane]);
            mma_f16(D + nt * 4, Ah + kt * 4, bfL[(kt * 8 + nt) * 32 + lane]);
        }
}
__device__ __forceinline__ void gemm3p(float* D, const uint32_t* Ah, const uint32_t* Al,
                                       const uint2* __restrict__ bfH,
                                       const uint2* __restrict__ bfL, int lane) {
#pragma unroll
    for (int kt = 0; kt < 4; kt++)
#pragma unroll
        for (int nt = 0; nt < 8; nt++) {
            uint2 bh = bfH[(kt * 8 + nt) * 32 + lane];
            mma_f16(D + nt * 4, Ah + kt * 4, bh);
            mma_f16(D + nt * 4, Al + kt * 4, bh);
            mma_f16(D + nt * 4, Ah + kt * 4, bfL[(kt * 8 + nt) * 32 + lane]);
        }
}

// build B fragments from 64x64 row-major W (logical indices); dstL may be null
__device__ __forceinline__ void build_bf(uint2* dstH, uint2* dstL,
                                         const float* __restrict__ W,
                                         int tid, int nth) {
    for (int i = tid; i < 1024; i += nth) {
        int kt = i >> 8, nt = (i >> 5) & 7, lane = i & 31;
        int g = lane >> 2, t = lane & 3;
        int col = 8 * nt + g;
        int k0  = 16 * kt + 2 * t;
        float w00 = W[(k0    ) * 64 + col];
        float w01 = W[(k0 + 1) * 64 + col];
        float w10 = W[(k0 + 8) * 64 + col];
        float w11 = W[(k0 + 9) * 64 + col];
        uint32_t h0, l0, h1, l1;
        pack_hl_f16(w00, w01, h0, l0);
        pack_hl_f16(w10, w11, h1, l1);
        int idx = (kt * 8 + nt) * 32 + lane;
        dstH[idx] = make_uint2(h0, h1);
        if (dstL) dstL[idx] = make_uint2(l0, l1);
    }
}

// ---------------- kernel 0: init reduction buffers ----------------
__global__ __launch_bounds__(256) void init_kernel() {
    int i = blockIdx.x * blockDim.x + threadIdx.x;
    if (i < Nn * 16) {
        g_s4[i]   = make_float4(0.f, 0.f, 0.f, 0.f);
        g_acc4[i] = make_float4(0.f, 0.f, 0.f, 0.f);
    }
}

// ---------------- kernel 1: node projections (mma, fp16 permuted outputs) ----------------
__global__ __launch_bounds__(256) void node_proj_kernel(
    const float* __restrict__ x,
    const float* __restrict__ Win,  const float* __restrict__ bin,
    const float* __restrict__ Wlin, const float* __restrict__ Wsrc,
    const float* __restrict__ Wdst)
{
    extern __shared__ __align__(16) char smem[];
    uint2*  sBF  = (uint2*)smem;                       // 8 x 1024 uint2 = 64KB
    float2* sBin = (float2*)(smem + 65536);
    const int tid = threadIdx.x;

    build_bf(sBF + 0 * 1024, sBF + 1 * 1024, Win,  tid, 256);
    build_bf(sBF + 2 * 1024, sBF + 3 * 1024, Wlin, tid, 256);
    build_bf(sBF + 4 * 1024, sBF + 5 * 1024, Wsrc, tid, 256);
    build_bf(sBF + 6 * 1024, sBF + 7 * 1024, Wdst, tid, 256);
    if (tid < 32) sBin[tid] = make_float2(bin[2 * tid], bin[2 * tid + 1]);
    __syncthreads();

    const int lane = tid & 31;
    const int g = lane >> 2, t = lane & 3;

    __half* outs[3] = { g_vh, g_ash, g_adh };

    const int nTiles = Nn / 16;  // 3125
    const int wStride = gridDim.x * 8;
    for (int tile = blockIdx.x * 8 + (tid >> 5); tile < nTiles; tile += wStride) {
        const int n0 = tile * 16;

        uint32_t Ah[16];
#pragma unroll
        for (int kt = 0; kt < 4; kt++)
#pragma unroll
            for (int half = 0; half < 2; half++)
#pragma unroll
                for (int h = 0; h < 2; h++) {
                    float2 xx = *(const float2*)&x[(n0 + g + 8 * h) * 64 + 16 * kt + 2 * t + 8 * half];
                    Ah[kt * 4 + h + 2 * half] = pack_f16x2(xx.x, xx.y);
                }

        float D[32];
#pragma unroll
        for (int i = 0; i < 32; i++) D[i] = 0.f;
        gemm2p(D, Ah, sBF + 0 * 1024, sBF + 1 * 1024, lane);

        uint32_t Ah2[16];
#pragma unroll
        for (int nt = 0; nt < 8; nt++) {
            float2 bb = sBin[4 * nt + t];
            int kt = nt >> 1, half = nt & 1, slot = kt * 4 + 2 * half;
            Ah2[slot]     = pack_f16x2(fmaxf(D[nt * 4 + 0] + bb.x, 0.f),
                                       fmaxf(D[nt * 4 + 1] + bb.y, 0.f));
            Ah2[slot + 1] = pack_f16x2(fmaxf(D[nt * 4 + 2] + bb.x, 0.f),
                                       fmaxf(D[nt * 4 + 3] + bb.y, 0.f));
        }

#pragma unroll
        for (int m = 0; m < 3; m++) {
#pragma unroll
            for (int i = 0; i < 32; i++) D[i] = 0.f;
            gemm2p(D, Ah2, sBF + (2 + 2 * m) * 1024, sBF + (3 + 2 * m) * 1024, lane);
            __half* o = outs[m];
#pragma unroll
            for (int ntp = 0; ntp < 4; ntp++) {
                int na = 2 * ntp, nb = na + 1;
                uint2 r0 = make_uint2(pack_f16x2(D[na * 4 + 0], D[na * 4 + 1]),
                                      pack_f16x2(D[nb * 4 + 0], D[nb * 4 + 1]));
                uint2 r8 = make_uint2(pack_f16x2(D[na * 4 + 2], D[na * 4 + 3]),
                                      pack_f16x2(D[nb * 4 + 2], D[nb * 4 + 3]));
                *(uint2*)(o + (n0 + g    ) * 64 + 16 * t + 4 * ntp) = r0;
                *(uint2*)(o + (n0 + g + 8) * 64 + 16 * t + 4 * ntp) = r8;
            }
        }
    }
}

// ---------------- kernel 2: fused edge kernel (pipelined, all GEMMs hi-only) ----------------
// smem: 3 B-frag arrays (Wp2 h, Wa1 h, Wa2 h) + Wp1 + biases
#define ESM_WP1   24576
#define ESM_BP2   25600
#define ESM_BA1   25856
#define ESM_BA2   26112
#define ESM_TOTAL 26624

__global__ __launch_bounds__(256, 2) void edge_fused_kernel(
    const float* __restrict__ pos, const int* __restrict__ ei,
    const float* __restrict__ Wp1, const float* __restrict__ bp1,
    const float* __restrict__ Wp2, const float* __restrict__ bp2,
    const float* __restrict__ Wa1, const float* __restrict__ ba1,
    const float* __restrict__ Wa2, const float* __restrict__ ba2)
{
    extern __shared__ __align__(16) char smem[];
    uint2*  sBF  = (uint2*)smem;
    float4* sWp1 = (float4*)(smem + ESM_WP1);
    float2* sBp2 = (float2*)(smem + ESM_BP2);
    float2* sBa1 = (float2*)(smem + ESM_BA1);
    float2* sBa2 = (float2*)(smem + ESM_BA2);

    const int tid = threadIdx.x;
    build_bf(sBF + 0 * 1024, (uint2*)0, Wp2, tid, 256);
    build_bf(sBF + 1 * 1024, (uint2*)0, Wa1, tid, 256);
    build_bf(sBF + 2 * 1024, (uint2*)0, Wa2, tid, 256);
    if (tid < 64)
        sWp1[tid] = make_float4(Wp1[tid], Wp1[64 + tid], Wp1[128 + tid], bp1[tid]);
    if (tid < 32) {
        sBp2[tid] = make_float2(bp2[2 * tid], bp2[2 * tid + 1]);
        sBa1[tid] = make_float2(ba1[2 * tid], ba1[2 * tid + 1]);
        sBa2[tid] = make_float2(ba2[2 * tid], ba2[2 * tid + 1]);
    }
    __syncthreads();

    const int lane = tid & 31;
    const int g = lane >> 2, t = lane & 3;

    const uint2* bfP2h = sBF + 0 * 1024;
    const uint2* bfA1h = sBF + 1 * 1024;
    const uint2* bfA2h = sBF + 2 * 1024;

    const int nTiles = Ee / 16;          // 50000
    const int wStride = gridDim.x * 8;

    int tile = blockIdx.x * 8 + (tid >> 5);

    // prefetch first tile's edge data (lanes 0-15 hold one edge each)
    int pS = 0, pD = 0;
    float pr0 = 0.f, pr1 = 0.f, pr2 = 0.f;
    if (tile < nTiles && lane < 16) {
        int e = tile * 16 + lane;
        pS = __ldg(&ei[e]);
        pD = __ldg(&ei[Ee + e]);
        pr0 = __ldg(&pos[pD * 3 + 0]) - __ldg(&pos[pS * 3 + 0]);
        pr1 = __ldg(&pos[pD * 3 + 1]) - __ldg(&pos[pS * 3 + 1]);
        pr2 = __ldg(&pos[pD * 3 + 2]) - __ldg(&pos[pS * 3 + 2]);
    }

    for (; tile < nTiles; tile += wStride) {
        // broadcast current tile's staged data via shfl (no smem, no sync)
        int sn[2], dn[2];
        float rl[2][3];
#pragma unroll
        for (int h = 0; h < 2; h++) {
            int src = g + 8 * h;
            sn[h]   = __shfl_sync(0xffffffffu, pS, src);
            dn[h]   = __shfl_sync(0xffffffffu, pD, src);
            rl[h][0] = __shfl_sync(0xffffffffu, pr0, src);
            rl[h][1] = __shfl_sync(0xffffffffu, pr1, src);
            rl[h][2] = __shfl_sync(0xffffffffu, pr2, src);
        }

        // hoist a_dst/a_src gathers: in flight during stage1 + GEMM1
        uint4 ad0a = __ldg((const uint4*)(g_adh + dn[0] * 64 + 16 * t));
        uint4 ad0b = __ldg((const uint4*)(g_adh + dn[0] * 64 + 16 * t + 8));
        uint4 as0a = __ldg((const uint4*)(g_ash + sn[0] * 64 + 16 * t));
        uint4 as0b = __ldg((const uint4*)(g_ash + sn[0] * 64 + 16 * t + 8));
        uint4 ad1a = __ldg((const uint4*)(g_adh + dn[1] * 64 + 16 * t));
        uint4 ad1b = __ldg((const uint4*)(g_adh + dn[1] * 64 + 16 * t + 8));
        uint4 as1a = __ldg((const uint4*)(g_ash + sn[1] * 64 + 16 * t));
        uint4 as1b = __ldg((const uint4*)(g_ash + sn[1] * 64 + 16 * t + 8));

        // stage 1: u = relu(rel @ Wp1 + bp1) -> A frags
        uint32_t Ah[16];
#pragma unroll
        for (int kt = 0; kt < 4; kt++)
#pragma unroll
            for (int half = 0; half < 2; half++) {
                int c0 = 16 * kt + 2 * t + 8 * half;
                float4 w0 = sWp1[c0];
                float4 w1 = sWp1[c0 + 1];
#pragma unroll
                for (int h = 0; h < 2; h++) {
                    float u0 = fmaxf(fmaf(rl[h][2], w0.z, fmaf(rl[h][1], w0.y,
                               fmaf(rl[h][0], w0.x, w0.w))), 0.f);
                    float u1 = fmaxf(fmaf(rl[h][2], w1.z, fmaf(rl[h][1], w1.y,
                               fmaf(rl[h][0], w1.x, w1.w))), 0.f);
                    Ah[kt * 4 + h + 2 * half] = pack_f16x2(u0, u1);
                }
            }

        // GEMM1: delta_raw = u @ Wp2 (hi-only)
        float D[32];
#pragma unroll
        for (int i = 0; i < 32; i++) D[i] = 0.f;
        gemm1p(D, Ah, bfP2h, lane);

        // prefetch next tile's edge data (covered by GEMM2/3)
        {
            int tn = tile + wStride;
            if (tn < nTiles && lane < 16) {
                int e = tn * 16 + lane;
                pS = __ldg(&ei[e]);
                pD = __ldg(&ei[Ee + e]);
                pr0 = __ldg(&pos[pD * 3 + 0]) - __ldg(&pos[pS * 3 + 0]);
                pr1 = __ldg(&pos[pD * 3 + 1]) - __ldg(&pos[pS * 3 + 1]);
                pr2 = __ldg(&pos[pD * 3 + 2]) - __ldg(&pos[pS * 3 + 2]);
            }
        }

        // G1 epilogue: delta = D + bp2 (packed fp16 regs); t = delta + ad - as -> A frags
        uint32_t wad0[8] = {ad0a.x, ad0a.y, ad0a.z, ad0a.w, ad0b.x, ad0b.y, ad0b.z, ad0b.w};
        uint32_t was0[8] = {as0a.x, as0a.y, as0a.z, as0a.w, as0b.x, as0b.y, as0b.z, as0b.w};
        uint32_t wad1[8] = {ad1a.x, ad1a.y, ad1a.z, ad1a.w, ad1b.x, ad1b.y, ad1b.z, ad1b.w};
        uint32_t was1[8] = {as1a.x, as1a.y, as1a.z, as1a.w, as1b.x, as1b.y, as1b.z, as1b.w};
        uint32_t dltp[16];
#pragma unroll
        for (int nt = 0; nt < 8; nt++) {
            float2 bb = sBp2[4 * nt + t];
            int kt = nt >> 1, half = nt & 1, slot = kt * 4 + 2 * half;
            float d00 = D[nt * 4 + 0] + bb.x, d01 = D[nt * 4 + 1] + bb.y;
            float d10 = D[nt * 4 + 2] + bb.x, d11 = D[nt * 4 + 3] + bb.y;
            dltp[2 * nt]     = pack_f16x2(d00, d01);
            dltp[2 * nt + 1] = pack_f16x2(d10, d11);
            float2 ad0 = h2f2(wad0[nt]), as0 = h2f2(was0[nt]);
            float2 ad1 = h2f2(wad1[nt]), as1 = h2f2(was1[nt]);
            Ah[slot]     = pack_f16x2(d00 + ad0.x - as0.x, d01 + ad0.y - as0.y);
            Ah[slot + 1] = pack_f16x2(d10 + ad1.x - as1.x, d11 + ad1.y - as1.y);
        }

        // hoist v gathers: in flight during GEMM2 + GEMM3
        uint4 v0a = __ldg((const uint4*)(g_vh + sn[0] * 64 + 16 * t));
        uint4 v0b = __ldg((const uint4*)(g_vh + sn[0] * 64 + 16 * t + 8));
        uint4 v1a = __ldg((const uint4*)(g_vh + sn[1] * 64 + 16 * t));
        uint4 v1b = __ldg((const uint4*)(g_vh + sn[1] * 64 + 16 * t + 8));

        // GEMM2: h2_raw = t @ Wa1
#pragma unroll
        for (int i = 0; i < 32; i++) D[i] = 0.f;
        gemm1p(D, Ah, bfA1h, lane);

        // G2 epilogue: h2 = relu(D + ba1)
#pragma unroll
        for (int nt = 0; nt < 8; nt++) {
            float2 bb = sBa1[4 * nt + t];
            int kt = nt >> 1, half = nt & 1, slot = kt * 4 + 2 * half;
            Ah[slot]     = pack_f16x2(fmaxf(D[nt * 4 + 0] + bb.x, 0.f),
                                      fmaxf(D[nt * 4 + 1] + bb.y, 0.f));
            Ah[slot + 1] = pack_f16x2(fmaxf(D[nt * 4 + 2] + bb.x, 0.f),
                                      fmaxf(D[nt * 4 + 3] + bb.y, 0.f));
        }

        // GEMM3: logit_raw = h2 @ Wa2
#pragma unroll
        for (int i = 0; i < 32; i++) D[i] = 0.f;
        gemm1p(D, Ah, bfA2h, lane);

        // G3 epilogue: e = exp(D + ba2); contiguous float4 reductions
        uint32_t wv0[8] = {v0a.x, v0a.y, v0a.z, v0a.w, v0b.x, v0b.y, v0b.z, v0b.w};
        uint32_t wv1[8] = {v1a.x, v1a.y, v1a.z, v1a.w, v1b.x, v1b.y, v1b.z, v1b.w};
        float* sp = (float*)g_s4;
        float* ap = (float*)g_acc4;
#pragma unroll
        for (int ntp = 0; ntp < 4; ntp++) {
            int na = 2 * ntp, nb = na + 1;
            float2 ba_a = sBa2[4 * na + t], ba_b = sBa2[4 * nb + t];
            float2 va0 = h2f2(wv0[na]), vb0 = h2f2(wv0[nb]);
            float2 va1 = h2f2(wv1[na]), vb1 = h2f2(wv1[nb]);
            float2 dna0 = h2f2(dltp[2 * na]),     dnb0 = h2f2(dltp[2 * nb]);
            float2 dna1 = h2f2(dltp[2 * na + 1]), dnb1 = h2f2(dltp[2 * nb + 1]);
            // edge 0 (row g)
            float e00 = __expf(D[na * 4 + 0] + ba_a.x);
            float e01 = __expf(D[na * 4 + 1] + ba_a.y);
            float e02 = __expf(D[nb * 4 + 0] + ba_b.x);
            float e03 = __expf(D[nb * 4 + 1] + ba_b.y);
            float a00 = e00 * (va0.x + dna0.x);
            float a01 = e01 * (va0.y + dna0.y);
            float a02 = e02 * (vb0.x + dnb0.x);
            float a03 = e03 * (vb0.y + dnb0.y);
            int off0 = dn[0] * 64 + 16 * t + 4 * ntp;
            red4((float4*)(sp + off0), e00, e01, e02, e03);
            red4((float4*)(ap + off0), a00, a01, a02, a03);
            // edge 1 (row g+8)
            float e10 = __expf(D[na * 4 + 2] + ba_a.x);
            float e11 = __expf(D[na * 4 + 3] + ba_a.y);
            float e12 = __expf(D[nb * 4 + 2] + ba_b.x);
            float e13 = __expf(D[nb * 4 + 3] + ba_b.y);
            float a10 = e10 * (va1.x + dna1.x);
            float a11 = e11 * (va1.y + dna1.y);
            float a12 = e12 * (vb1.x + dnb1.x);
            float a13 = e13 * (vb1.y + dnb1.y);
            int off1 = dn[1] * 64 + 16 * t + 4 * ntp;
            red4((float4*)(sp + off1), e10, e11, e12, e13);
            red4((float4*)(ap + off1), a10, a11, a12, a13);
        }
    }
}

// ---------------- kernel 3: normalize + lin_out + relu (mma) ----------------
__global__ __launch_bounds__(256) void node_out_kernel(
    const float* __restrict__ Wout, const float* __restrict__ bout,
    float* __restrict__ out)
{
    extern __shared__ __align__(16) char smem[];
    uint2*  sBF  = (uint2*)smem;                  // Wout hi + lo = 16KB
    float2* sB   = (float2*)(smem + 16384);
    const int tid = threadIdx.x;
    build_bf(sBF, sBF + 1024, Wout, tid, 256);
    if (tid < 32) sB[tid] = make_float2(bout[2 * tid], bout[2 * tid + 1]);
    __syncthreads();

    const int lane = tid & 31;
    const int g = lane >> 2, t = lane & 3;
    const float* accp = (const float*)g_acc4;
    const float* ssp  = (const float*)g_s4;

    const int nTiles = Nn / 16;  // 3125
    const int wStride = gridDim.x * 8;
    for (int tile = blockIdx.x * 8 + (tid >> 5); tile < nTiles; tile += wStride) {
        const int n0 = tile * 16;

        float rg0[16], rg1[16];
#pragma unroll
        for (int q = 0; q < 4; q++) {
            float4 a0 = *(const float4*)(accp + (n0 + g) * 64 + 16 * t + 4 * q);
            float4 s0 = *(const float4*)(ssp  + (n0 + g) * 64 + 16 * t + 4 * q);
            rg0[4 * q + 0] = a0.x / (s0.x + 1e-16f);
            rg0[4 * q + 1] = a0.y / (s0.y + 1e-16f);
            rg0[4 * q + 2] = a0.z / (s0.z + 1e-16f);
            rg0[4 * q + 3] = a0.w / (s0.w + 1e-16f);
            float4 a1 = *(const float4*)(accp + (n0 + g + 8) * 64 + 16 * t + 4 * q);
            float4 s1 = *(const float4*)(ssp  + (n0 + g + 8) * 64 + 16 * t + 4 * q);
            rg1[4 * q + 0] = a1.x / (s1.x + 1e-16f);
            rg1[4 * q + 1] = a1.y / (s1.y + 1e-16f);
            rg1[4 * q + 2] = a1.z / (s1.z + 1e-16f);
            rg1[4 * q + 3] = a1.w / (s1.w + 1e-16f);
        }

        uint32_t Ah[16], Al[16];
#pragma unroll
        for (int nt = 0; nt < 8; nt++) {
            int kt = nt >> 1, half = nt & 1, slot = kt * 4 + 2 * half;
            pack_hl_f16(rg0[2 * nt], rg0[2 * nt + 1], Ah[slot],     Al[slot]);
            pack_hl_f16(rg1[2 * nt], rg1[2 * nt + 1], Ah[slot + 1], Al[slot + 1]);
        }

        float D[32];
#pragma unroll
        for (int i = 0; i < 32; i++) D[i] = 0.f;
        gemm3p(D, Ah, Al, sBF, sBF + 1024, lane);

#pragma unroll
        for (int nt = 0; nt < 8; nt++) {
            int c0 = 8 * nt + 2 * t;
            float2 bb = sB[4 * nt + t];
            *(float2*)&out[(n0 + g    ) * 64 + c0] =
                make_float2(fmaxf(D[nt * 4 + 0] + bb.x, 0.f),
                            fmaxf(D[nt * 4 + 1] + bb.y, 0.f));
            *(float2*)&out[(n0 + g + 8) * 64 + c0] =
                make_float2(fmaxf(D[nt * 4 + 2] + bb.x, 0.f),
                            fmaxf(D[nt * 4 + 3] + bb.y, 0.f));
        }
    }
}

// ---------------- launch ----------------
extern "C" void kernel_launch(void* const* d_in, const int* in_sizes, int n_in,
                              void* d_out, int out_size)
{
    const float* x    = (const float*)d_in[0];
    const float* pos  = (const float*)d_in[1];
    const int*   ei   = (const int*)  d_in[2];
    const float* Win  = (const float*)d_in[3];
    const float* bin  = (const float*)d_in[4];
    const float* Wlin = (const float*)d_in[5];
    const float* Wsrc = (const float*)d_in[6];
    const float* Wdst = (const float*)d_in[7];
    const float* Wp1  = (const float*)d_in[8];
    const float* bp1  = (const float*)d_in[9];
    const float* Wp2  = (const float*)d_in[10];
    const float* bp2  = (const float*)d_in[11];
    const float* Wa1  = (const float*)d_in[12];
    const float* ba1  = (const float*)d_in[13];
    const float* Wa2  = (const float*)d_in[14];
    const float* ba2  = (const float*)d_in[15];
    const float* Wout = (const float*)d_in[16];
    const float* bout = (const float*)d_in[17];

    const int projSmem = 65536 + 256;
    const int outSmem  = 16384 + 256;
    cudaFuncSetAttribute(node_proj_kernel,  cudaFuncAttributeMaxDynamicSharedMemorySize, projSmem);
    cudaFuncSetAttribute(edge_fused_kernel, cudaFuncAttributeMaxDynamicSharedMemorySize, ESM_TOTAL);
    cudaFuncSetAttribute(node_out_kernel,   cudaFuncAttributeMaxDynamicSharedMemorySize, outSmem);

    init_kernel<<<(Nn * 16 + 255) / 256, 256>>>();
    node_proj_kernel<<<296, 256, projSmem>>>(x, Win, bin, Wlin, Wsrc, Wdst);
    edge_fused_kernel<<<296, 256, ESM_TOTAL>>>(pos, ei, Wp1, bp1, Wp2, bp2,
                                               Wa1, ba1, Wa2, ba2);
    node_out_kernel<<<296, 256, outSmem>>>(Wout, bout, (float*)d_out);
}